// round 7
// baseline (speedup 1.0000x reference)
#include <cuda_runtime.h>

// GCN 2-layer, CSR-gather, fused gather+FFMA2-double-GEMM:
//   count = indegree;  dinv = rsqrt(1+count);  CSR rows allocated by
//   warp-aggregated atomicAdd (row order irrelevant, only contiguity needed)
//   k_fused (per warp, 8 nodes):
//     a  = (x[d]*dinv[d] + sum x[s]*dinv[s]) * dinv[d]   (in-kernel gather)
//     h1 = relu(a @ W1 + b1)     (smem, FFMA2)
//     ts = (h1 @ W2) * dinv      -> g_ts
//   k_gather2: out = (ts[d] + sum ts[s]) * dinv[d] + b2
// edge_index int32.  Device symbols touched ONLY from device code (GB300 ATS
// makes host-side symbol addresses silently read host memory).

#define NMAX 100000
#define EMAX 1600000
#define F 64
#define HID 128

typedef unsigned long long ull;

__device__ float g_dinv[NMAX];
__device__ float g_ts[NMAX * F];

__device__ int g_count[NMAX];
__device__ int g_row_start[NMAX];
__device__ int g_cursor[NMAX];
__device__ int g_csr[EMAX];
__device__ int g_total;

// ---------------------------------------------------------------- f32x2 helpers
__device__ __forceinline__ ull pack2(float lo, float hi) {
    ull r;
    asm("mov.b64 %0, {%1, %2};" : "=l"(r) : "f"(lo), "f"(hi));
    return r;
}
__device__ __forceinline__ void unpack2(ull v, float& lo, float& hi) {
    asm("mov.b64 {%0, %1}, %2;" : "=f"(lo), "=f"(hi) : "l"(v));
}
__device__ __forceinline__ ull ffma2(ull a, ull b, ull c) {
    ull d;
    asm("fma.rn.f32x2 %0, %1, %2, %3;" : "=l"(d) : "l"(a), "l"(b), "l"(c));
    return d;
}

// ---------------------------------------------------------------- CSR build
__global__ void k_zero(int n) {
    int i = blockIdx.x * blockDim.x + threadIdx.x;
    if (i == 0) g_total = 0;
    if (i < n) g_count[i] = 0;
}

__global__ void k_hist(const int* __restrict__ dst, int E) {
    int i = blockIdx.x * blockDim.x + threadIdx.x;
    if (i < E) atomicAdd(&g_count[dst[i]], 1);
}

// Row allocation: warp-inclusive scan of counts + one atomicAdd per warp.
// Also computes dinv.  (CSR row placement order is irrelevant.)
__global__ void k_alloc(int n) {
    int i = blockIdx.x * blockDim.x + threadIdx.x;
    int lane = threadIdx.x & 31;
    int cnt = (i < n) ? g_count[i] : 0;
    int sum = cnt;
#pragma unroll
    for (int off = 1; off < 32; off <<= 1) {
        int v = __shfl_up_sync(0xffffffffu, sum, off);
        if (lane >= off) sum += v;
    }
    int total = __shfl_sync(0xffffffffu, sum, 31);
    int base = 0;
    if (lane == 0) base = atomicAdd(&g_total, total);
    base = __shfl_sync(0xffffffffu, base, 0);
    int start = base + sum - cnt;
    if (i < n) {
        g_row_start[i] = start;
        g_cursor[i] = start;
        g_dinv[i] = rsqrtf(1.0f + (float)cnt);
    }
}

__global__ void k_permute(const int* __restrict__ src,
                          const int* __restrict__ dst, int E) {
    int i = blockIdx.x * blockDim.x + threadIdx.x;
    if (i < E) {
        int pos = atomicAdd(&g_cursor[dst[i]], 1);
        g_csr[pos] = src[i];
    }
}

// ---------------------------------------------------------------- fused kernel
// Warp handles 8 nodes: gather (from x, scale dinv[s]) -> aT -> FFMA2 GEMM1
// -> relu -> hT -> FFMA2 GEMM2 -> ts*dinv -> g_ts.
// smem (floats): W1s[8192] | W2s[8192] | b1s[128] | aT[6][64*10] | hT[6][128*10]
#define FG_WARPS 6
#define FG_THREADS (FG_WARPS * 32)
#define ATS 10
#define OFF_W2 8192
#define OFF_B1 16384
#define OFF_AT 16512
#define OFF_HT (OFF_AT + FG_WARPS * (F * ATS))
#define FG_FLOATS (OFF_HT + FG_WARPS * (HID * ATS))
#define FG_BYTES (FG_FLOATS * 4)

__global__ void __launch_bounds__(FG_THREADS, 2)
k_fused(const float* __restrict__ x, const float* __restrict__ W1,
        const float* __restrict__ b1, const float* __restrict__ W2, int n) {
    extern __shared__ float smem[];
    float* W1s = smem;
    float* W2s = smem + OFF_W2;
    float* b1s = smem + OFF_B1;
    int tid = threadIdx.x;
    int warp = tid >> 5;
    int lane = tid & 31;

    for (int j = tid; j < (F * HID) / 4; j += FG_THREADS)
        ((float4*)W1s)[j] = ((const float4*)W1)[j];
    for (int j = tid; j < (HID * F) / 4; j += FG_THREADS)
        ((float4*)W2s)[j] = ((const float4*)W2)[j];
    for (int j = tid; j < HID; j += FG_THREADS) b1s[j] = b1[j];
    __syncthreads();

    int nbase = (blockIdx.x * FG_WARPS + warp) * 8;
    if (nbase >= n) return;
    float* aTw = smem + OFF_AT + warp * (F * ATS);
    float* hTw = smem + OFF_HT + warp * (HID * ATS);

    // ---- in-kernel gather of 8 nodes (whole warp per node)
    const float4* b4 = (const float4*)x;
    int c = lane & 15;
    int half = lane >> 4;
#pragma unroll 1
    for (int ni = 0; ni < 8; ni++) {
        int d = nbase + ni;
        float4 acc = make_float4(0.f, 0.f, 0.f, 0.f);
        if (d < n) {
            int start = g_row_start[d];
            int end = start + g_count[d];
            int e = start + half;
            for (; e + 2 < end; e += 4) {
                int s0 = __ldg(&g_csr[e]);
                int s1 = __ldg(&g_csr[e + 2]);
                float4 v0 = b4[(size_t)s0 * 16 + c];
                float4 v1 = b4[(size_t)s1 * 16 + c];
                float dv0 = g_dinv[s0], dv1 = g_dinv[s1];
                acc.x += v0.x * dv0 + v1.x * dv1;
                acc.y += v0.y * dv0 + v1.y * dv1;
                acc.z += v0.z * dv0 + v1.z * dv1;
                acc.w += v0.w * dv0 + v1.w * dv1;
            }
            if (e < end) {
                int s = __ldg(&g_csr[e]);
                float4 v = b4[(size_t)s * 16 + c];
                float dv = g_dinv[s];
                acc.x += v.x * dv; acc.y += v.y * dv;
                acc.z += v.z * dv; acc.w += v.w * dv;
            }
        }
        acc.x += __shfl_down_sync(0xffffffffu, acc.x, 16);
        acc.y += __shfl_down_sync(0xffffffffu, acc.y, 16);
        acc.z += __shfl_down_sync(0xffffffffu, acc.z, 16);
        acc.w += __shfl_down_sync(0xffffffffu, acc.w, 16);
        if (half == 0) {
            float dvd = (d < n) ? g_dinv[d] : 0.f;
            if (d < n) {
                float4 sv = b4[(size_t)d * 16 + c];
                acc.x += sv.x * dvd; acc.y += sv.y * dvd;
                acc.z += sv.z * dvd; acc.w += sv.w * dvd;
            }
            acc.x *= dvd; acc.y *= dvd; acc.z *= dvd; acc.w *= dvd;
            aTw[(4 * c + 0) * ATS + ni] = acc.x;
            aTw[(4 * c + 1) * ATS + ni] = acc.y;
            aTw[(4 * c + 2) * ATS + ni] = acc.z;
            aTw[(4 * c + 3) * ATS + ni] = acc.w;
        }
    }
    __syncwarp();

    // ---- layer 1: acc[p][j] = packed (node 2p, 2p+1) at col lane+32j
    ull acc1[4][4];
#pragma unroll
    for (int p = 0; p < 4; p++)
#pragma unroll
        for (int j = 0; j < 4; j++) acc1[p][j] = 0ull;

#pragma unroll 4
    for (int k = 0; k < F; k++) {
        const ull* ar = (const ull*)(aTw + k * ATS);
        ull a0 = ar[0], a1 = ar[1], a2 = ar[2], a3 = ar[3];
        const float* wr = W1s + k * HID + lane;
        ull w0 = pack2(wr[0], wr[0]);
        ull w1 = pack2(wr[32], wr[32]);
        ull w2 = pack2(wr[64], wr[64]);
        ull w3 = pack2(wr[96], wr[96]);
        acc1[0][0] = ffma2(a0, w0, acc1[0][0]);
        acc1[0][1] = ffma2(a0, w1, acc1[0][1]);
        acc1[0][2] = ffma2(a0, w2, acc1[0][2]);
        acc1[0][3] = ffma2(a0, w3, acc1[0][3]);
        acc1[1][0] = ffma2(a1, w0, acc1[1][0]);
        acc1[1][1] = ffma2(a1, w1, acc1[1][1]);
        acc1[1][2] = ffma2(a1, w2, acc1[1][2]);
        acc1[1][3] = ffma2(a1, w3, acc1[1][3]);
        acc1[2][0] = ffma2(a2, w0, acc1[2][0]);
        acc1[2][1] = ffma2(a2, w1, acc1[2][1]);
        acc1[2][2] = ffma2(a2, w2, acc1[2][2]);
        acc1[2][3] = ffma2(a2, w3, acc1[2][3]);
        acc1[3][0] = ffma2(a3, w0, acc1[3][0]);
        acc1[3][1] = ffma2(a3, w1, acc1[3][1]);
        acc1[3][2] = ffma2(a3, w2, acc1[3][2]);
        acc1[3][3] = ffma2(a3, w3, acc1[3][3]);
    }

    // bias + relu -> hT
#pragma unroll
    for (int j = 0; j < 4; j++) {
        float bb = b1s[lane + 32 * j];
        float* hrow = hTw + (lane + 32 * j) * ATS;
#pragma unroll
        for (int p = 0; p < 4; p++) {
            float lo, hi;
            unpack2(acc1[p][j], lo, hi);
            lo = fmaxf(lo + bb, 0.f);
            hi = fmaxf(hi + bb, 0.f);
            ((ull*)hrow)[p] = pack2(lo, hi);
        }
    }
    __syncwarp();

    // ---- layer 2
    ull t0[4], t1[4];
#pragma unroll
    for (int p = 0; p < 4; p++) { t0[p] = 0ull; t1[p] = 0ull; }

#pragma unroll 2
    for (int k = 0; k < HID; k++) {
        const ull* hr = (const ull*)(hTw + k * ATS);
        ull h0 = hr[0], h1 = hr[1], h2 = hr[2], h3 = hr[3];
        float u0 = W2s[k * F + lane];
        float u1 = W2s[k * F + lane + 32];
        ull up0 = pack2(u0, u0);
        ull up1 = pack2(u1, u1);
        t0[0] = ffma2(h0, up0, t0[0]);
        t0[1] = ffma2(h1, up0, t0[1]);
        t0[2] = ffma2(h2, up0, t0[2]);
        t0[3] = ffma2(h3, up0, t0[3]);
        t1[0] = ffma2(h0, up1, t1[0]);
        t1[1] = ffma2(h1, up1, t1[1]);
        t1[2] = ffma2(h2, up1, t1[2]);
        t1[3] = ffma2(h3, up1, t1[3]);
    }

    // ts = t * dinv -> g_ts
#pragma unroll
    for (int p = 0; p < 4; p++) {
        int n0 = nbase + 2 * p;
        int n1 = n0 + 1;
        float lo0, hi0, lo1, hi1;
        unpack2(t0[p], lo0, hi0);
        unpack2(t1[p], lo1, hi1);
        if (n0 < n) {
            float dv = g_dinv[n0];
            g_ts[(size_t)n0 * F + lane] = lo0 * dv;
            g_ts[(size_t)n0 * F + 32 + lane] = lo1 * dv;
        }
        if (n1 < n) {
            float dv = g_dinv[n1];
            g_ts[(size_t)n1 * F + lane] = hi0 * dv;
            g_ts[(size_t)n1 * F + 32 + lane] = hi1 * dv;
        }
    }
}

// ---------------------------------------------------------------- gather2
// out = (ts[d] + sum ts[s]) * dinv[d] + b2.  One warp per dst node.
__global__ void __launch_bounds__(256)
k_gather2(const float* __restrict__ b2, float* __restrict__ out, int n) {
    int gwarp = (blockIdx.x * blockDim.x + threadIdx.x) >> 5;
    if (gwarp >= n) return;
    int lane = threadIdx.x & 31;
    int d = gwarp;
    int c = lane & 15;
    int half = lane >> 4;

    const float4* b4 = (const float4*)g_ts;
    float4 acc = make_float4(0.f, 0.f, 0.f, 0.f);

    int start = g_row_start[d];
    int end = start + g_count[d];
    int e = start + half;
    for (; e + 2 < end; e += 4) {
        int s0 = __ldg(&g_csr[e]);
        int s1 = __ldg(&g_csr[e + 2]);
        float4 v0 = b4[(size_t)s0 * 16 + c];
        float4 v1 = b4[(size_t)s1 * 16 + c];
        acc.x += v0.x + v1.x;
        acc.y += v0.y + v1.y;
        acc.z += v0.z + v1.z;
        acc.w += v0.w + v1.w;
    }
    if (e < end) {
        int s = __ldg(&g_csr[e]);
        float4 v = b4[(size_t)s * 16 + c];
        acc.x += v.x; acc.y += v.y; acc.z += v.z; acc.w += v.w;
    }

    acc.x += __shfl_down_sync(0xffffffffu, acc.x, 16);
    acc.y += __shfl_down_sync(0xffffffffu, acc.y, 16);
    acc.z += __shfl_down_sync(0xffffffffu, acc.z, 16);
    acc.w += __shfl_down_sync(0xffffffffu, acc.w, 16);

    if (half == 0) {
        float dvd = g_dinv[d];
        float4 sv = b4[(size_t)d * 16 + c];
        acc.x += sv.x; acc.y += sv.y; acc.z += sv.z; acc.w += sv.w;
        float4 bb = ((const float4*)b2)[c];
        acc.x = acc.x * dvd + bb.x;
        acc.y = acc.y * dvd + bb.y;
        acc.z = acc.z * dvd + bb.z;
        acc.w = acc.w * dvd + bb.w;
        ((float4*)out)[(size_t)d * 16 + c] = acc;
    }
}

// ---------------------------------------------------------------- launch
extern "C" void kernel_launch(void* const* d_in, const int* in_sizes, int n_in,
                              void* d_out, int out_size) {
    const float* x  = (const float*)d_in[0];
    const int* ei   = (const int*)d_in[1];   // int32 edge_index [2, E]
    const float* W1 = (const float*)d_in[2];
    const float* b1 = (const float*)d_in[3];
    const float* W2 = (const float*)d_in[4];
    const float* b2 = (const float*)d_in[5];
    float* out      = (float*)d_out;

    int n = in_sizes[0] / F;   // 100000
    int E = in_sizes[1] / 2;   // 1600000
    const int* src = ei;
    const int* dst = ei + E;

    cudaFuncSetAttribute(k_fused, cudaFuncAttributeMaxDynamicSharedMemorySize,
                         FG_BYTES);

    int nbN = (n + 255) / 256;
    int nbE = (E + 255) / 256;

    // CSR build
    k_zero<<<nbN, 256>>>(n);
    k_hist<<<nbE, 256>>>(dst, E);
    k_alloc<<<nbN, 256>>>(n);
    k_permute<<<nbE, 256>>>(src, dst, E);

    // fused gather1 + double GEMM
    int fg_blocks = ((n + 7) / 8 + FG_WARPS - 1) / FG_WARPS;
    k_fused<<<fg_blocks, FG_THREADS, FG_BYTES>>>(x, W1, b1, W2, n);

    // layer 2 aggregation + epilogue
    int gth_blocks = (n * 32 + 255) / 256;
    k_gather2<<<gth_blocks, 256>>>(b2, out, n);
}

// round 8
// speedup vs baseline: 1.2210x; 1.2210x over previous
#include <cuda_runtime.h>

// GCN 2-layer, CSR-gather aggregation, FFMA2 double-GEMM (R6 structure +
// single-kernel row allocation):
//   count = indegree;  dinv = rsqrt(1+count);  CSR rows via warp-aggregated
//   atomicAdd allocation (row order irrelevant, only contiguity needed)
//   a    = (x[d]*dinv[d] + sum x[s]*dinv[s]) * dinv[d]   (gather1 -> g_agg)
//   h1   = relu(a @ W1 + b1)   }  fused GEMM kernel, h1 in smem
//   ts   = (h1 @ W2) * dinv    }  -> g_ts
//   out  = (ts[d] + sum ts[s]) * dinv[d] + b2            (gather2 -> out)
// edge_index int32.  Device symbols touched ONLY from device code (GB300 ATS
// makes host-side symbol addresses silently read host memory).

#define NMAX 100000
#define EMAX 1600000
#define F 64
#define HID 128

typedef unsigned long long ull;

__device__ float g_dinv[NMAX];
__device__ float g_agg[NMAX * F];
__device__ float g_ts[NMAX * F];

__device__ int g_count[NMAX];
__device__ int g_row_start[NMAX];
__device__ int g_cursor[NMAX];
__device__ int g_csr[EMAX];
__device__ int g_total;

// ---------------------------------------------------------------- f32x2 helpers
__device__ __forceinline__ ull pack2(float lo, float hi) {
    ull r;
    asm("mov.b64 %0, {%1, %2};" : "=l"(r) : "f"(lo), "f"(hi));
    return r;
}
__device__ __forceinline__ void unpack2(ull v, float& lo, float& hi) {
    asm("mov.b64 {%0, %1}, %2;" : "=f"(lo), "=f"(hi) : "l"(v));
}
__device__ __forceinline__ ull ffma2(ull a, ull b, ull c) {
    ull d;
    asm("fma.rn.f32x2 %0, %1, %2, %3;" : "=l"(d) : "l"(a), "l"(b), "l"(c));
    return d;
}

// ---------------------------------------------------------------- CSR build
__global__ void k_zero(int n) {
    int i = blockIdx.x * blockDim.x + threadIdx.x;
    if (i == 0) g_total = 0;
    if (i < n) g_count[i] = 0;
}

__global__ void k_hist(const int* __restrict__ dst, int E) {
    int i = blockIdx.x * blockDim.x + threadIdx.x;
    if (i < E) atomicAdd(&g_count[__ldg(&dst[i])], 1);
}

// Row allocation: warp-inclusive scan of counts + one atomicAdd per warp.
// Also computes dinv.  (CSR row placement order is irrelevant.)
__global__ void k_alloc(int n) {
    int i = blockIdx.x * blockDim.x + threadIdx.x;
    int lane = threadIdx.x & 31;
    int cnt = (i < n) ? g_count[i] : 0;
    int sum = cnt;
#pragma unroll
    for (int off = 1; off < 32; off <<= 1) {
        int v = __shfl_up_sync(0xffffffffu, sum, off);
        if (lane >= off) sum += v;
    }
    int total = __shfl_sync(0xffffffffu, sum, 31);
    int base = 0;
    if (lane == 0) base = atomicAdd(&g_total, total);
    base = __shfl_sync(0xffffffffu, base, 0);
    int start = base + sum - cnt;
    if (i < n) {
        g_row_start[i] = start;
        g_cursor[i] = start;
        g_dinv[i] = rsqrtf(1.0f + (float)cnt);
    }
}

// 2 edges per thread: two independent atomic chains in flight.
__global__ void k_permute(const int* __restrict__ src,
                          const int* __restrict__ dst, int E) {
    int i = (blockIdx.x * blockDim.x + threadIdx.x) * 2;
    if (i + 1 < E) {
        int d0 = __ldg(&dst[i]);
        int d1 = __ldg(&dst[i + 1]);
        int s0 = __ldg(&src[i]);
        int s1 = __ldg(&src[i + 1]);
        int p0 = atomicAdd(&g_cursor[d0], 1);
        int p1 = atomicAdd(&g_cursor[d1], 1);
        g_csr[p0] = s0;
        g_csr[p1] = s1;
    } else if (i < E) {
        int p = atomicAdd(&g_cursor[__ldg(&dst[i])], 1);
        g_csr[p] = __ldg(&src[i]);
    }
}

// ---------------------------------------------------------------- gathers
// One warp per dst node. Lanes 0-15: chunk c over even edges; lanes 16-31:
// chunk c over odd edges; halves merged via shfl_down(16).
// MODE 0: source = x (param), rows scaled by dinv[s]; *dinv[d] -> g_agg.
// MODE 1: source = g_ts; acc*dinv[d] + b2 -> out (param).
template <int MODE>
__global__ void __launch_bounds__(256)
k_gather(const float* __restrict__ xparam, const float* __restrict__ b2,
         float* __restrict__ outparam, int n) {
    int gwarp = (blockIdx.x * blockDim.x + threadIdx.x) >> 5;
    if (gwarp >= n) return;
    int lane = threadIdx.x & 31;
    int d = gwarp;
    int c = lane & 15;
    int half = lane >> 4;

    const float4* b4 = (MODE == 0) ? (const float4*)xparam
                                   : (const float4*)g_ts;
    float4 acc = make_float4(0.f, 0.f, 0.f, 0.f);

    int start = g_row_start[d];
    int end = start + g_count[d];
    int e = start + half;
    for (; e + 2 < end; e += 4) {
        int s0 = __ldg(&g_csr[e]);
        int s1 = __ldg(&g_csr[e + 2]);
        float4 v0 = b4[(size_t)s0 * 16 + c];
        float4 v1 = b4[(size_t)s1 * 16 + c];
        if (MODE == 0) {
            float dv0 = g_dinv[s0], dv1 = g_dinv[s1];
            acc.x += v0.x * dv0 + v1.x * dv1;
            acc.y += v0.y * dv0 + v1.y * dv1;
            acc.z += v0.z * dv0 + v1.z * dv1;
            acc.w += v0.w * dv0 + v1.w * dv1;
        } else {
            acc.x += v0.x + v1.x;
            acc.y += v0.y + v1.y;
            acc.z += v0.z + v1.z;
            acc.w += v0.w + v1.w;
        }
    }
    if (e < end) {
        int s = __ldg(&g_csr[e]);
        float4 v = b4[(size_t)s * 16 + c];
        if (MODE == 0) {
            float dv = g_dinv[s];
            acc.x += v.x * dv; acc.y += v.y * dv;
            acc.z += v.z * dv; acc.w += v.w * dv;
        } else {
            acc.x += v.x; acc.y += v.y; acc.z += v.z; acc.w += v.w;
        }
    }

    acc.x += __shfl_down_sync(0xffffffffu, acc.x, 16);
    acc.y += __shfl_down_sync(0xffffffffu, acc.y, 16);
    acc.z += __shfl_down_sync(0xffffffffu, acc.z, 16);
    acc.w += __shfl_down_sync(0xffffffffu, acc.w, 16);

    if (half == 0) {
        float dvd = g_dinv[d];
        float4 sv = b4[(size_t)d * 16 + c];
        if (MODE == 0) {
            acc.x += sv.x * dvd; acc.y += sv.y * dvd;
            acc.z += sv.z * dvd; acc.w += sv.w * dvd;
        } else {
            acc.x += sv.x; acc.y += sv.y; acc.z += sv.z; acc.w += sv.w;
        }
        acc.x *= dvd; acc.y *= dvd; acc.z *= dvd; acc.w *= dvd;
        float4* dst4 = (MODE == 0) ? (float4*)g_agg : (float4*)outparam;
        if (MODE == 1) {
            float4 bb = ((const float4*)b2)[c];
            acc.x += bb.x; acc.y += bb.y; acc.z += bb.z; acc.w += bb.w;
        }
        dst4[(size_t)d * 16 + c] = acc;
    }
}

// ---------------------------------------------------------------- fused GEMMs
// Warp handles 8 nodes.  acc pairs adjacent nodes -> fma.rn.f32x2.
// smem (floats): W1s[8192] | W2s[8192] | b1s[128] | aT[6][64*10] | hT[6][128*10]
#define FG_WARPS 6
#define FG_THREADS (FG_WARPS * 32)
#define ATS 10
#define OFF_W2 8192
#define OFF_B1 16384
#define OFF_AT 16512
#define OFF_HT (OFF_AT + FG_WARPS * (F * ATS))
#define FG_FLOATS (OFF_HT + FG_WARPS * (HID * ATS))
#define FG_BYTES (FG_FLOATS * 4)

__global__ void __launch_bounds__(FG_THREADS, 2)
k_fused(const float* __restrict__ W1, const float* __restrict__ b1,
        const float* __restrict__ W2, int n) {
    extern __shared__ float smem[];
    float* W1s = smem;
    float* W2s = smem + OFF_W2;
    float* b1s = smem + OFF_B1;
    int tid = threadIdx.x;
    int warp = tid >> 5;
    int lane = tid & 31;

    for (int j = tid; j < (F * HID) / 4; j += FG_THREADS)
        ((float4*)W1s)[j] = ((const float4*)W1)[j];
    for (int j = tid; j < (HID * F) / 4; j += FG_THREADS)
        ((float4*)W2s)[j] = ((const float4*)W2)[j];
    for (int j = tid; j < HID; j += FG_THREADS) b1s[j] = b1[j];
    __syncthreads();

    int nbase = (blockIdx.x * FG_WARPS + warp) * 8;
    if (nbase >= n) return;
    float* aTw = smem + OFF_AT + warp * (F * ATS);
    float* hTw = smem + OFF_HT + warp * (HID * ATS);

    // stage a (transposed): aT row k holds 8 nodes' a[k]
#pragma unroll
    for (int ni = 0; ni < 8; ni++) {
        int node = nbase + ni;
        float a0 = 0.f, a1 = 0.f;
        if (node < n) {
            a0 = g_agg[(size_t)node * F + lane];
            a1 = g_agg[(size_t)node * F + 32 + lane];
        }
        aTw[lane * ATS + ni] = a0;
        aTw[(lane + 32) * ATS + ni] = a1;
    }
    __syncwarp();

    // ---- layer 1: acc1[p][j] = packed (node 2p, 2p+1) at col lane+32j
    ull acc1[4][4];
#pragma unroll
    for (int p = 0; p < 4; p++)
#pragma unroll
        for (int j = 0; j < 4; j++) acc1[p][j] = 0ull;

#pragma unroll 4
    for (int k = 0; k < F; k++) {
        const ull* ar = (const ull*)(aTw + k * ATS);
        ull a0 = ar[0], a1 = ar[1], a2 = ar[2], a3 = ar[3];
        const float* wr = W1s + k * HID + lane;
        ull w0 = pack2(wr[0], wr[0]);
        ull w1 = pack2(wr[32], wr[32]);
        ull w2 = pack2(wr[64], wr[64]);
        ull w3 = pack2(wr[96], wr[96]);
        acc1[0][0] = ffma2(a0, w0, acc1[0][0]);
        acc1[0][1] = ffma2(a0, w1, acc1[0][1]);
        acc1[0][2] = ffma2(a0, w2, acc1[0][2]);
        acc1[0][3] = ffma2(a0, w3, acc1[0][3]);
        acc1[1][0] = ffma2(a1, w0, acc1[1][0]);
        acc1[1][1] = ffma2(a1, w1, acc1[1][1]);
        acc1[1][2] = ffma2(a1, w2, acc1[1][2]);
        acc1[1][3] = ffma2(a1, w3, acc1[1][3]);
        acc1[2][0] = ffma2(a2, w0, acc1[2][0]);
        acc1[2][1] = ffma2(a2, w1, acc1[2][1]);
        acc1[2][2] = ffma2(a2, w2, acc1[2][2]);
        acc1[2][3] = ffma2(a2, w3, acc1[2][3]);
        acc1[3][0] = ffma2(a3, w0, acc1[3][0]);
        acc1[3][1] = ffma2(a3, w1, acc1[3][1]);
        acc1[3][2] = ffma2(a3, w2, acc1[3][2]);
        acc1[3][3] = ffma2(a3, w3, acc1[3][3]);
    }

    // bias + relu -> hT (row = output col 0..127, entries = 8 nodes)
#pragma unroll
    for (int j = 0; j < 4; j++) {
        float bb = b1s[lane + 32 * j];
        float* hrow = hTw + (lane + 32 * j) * ATS;
#pragma unroll
        for (int p = 0; p < 4; p++) {
            float lo, hi;
            unpack2(acc1[p][j], lo, hi);
            lo = fmaxf(lo + bb, 0.f);
            hi = fmaxf(hi + bb, 0.f);
            ((ull*)hrow)[p] = pack2(lo, hi);
        }
    }
    __syncwarp();

    // ---- layer 2: out cols lane, lane+32
    ull t0[4], t1[4];
#pragma unroll
    for (int p = 0; p < 4; p++) { t0[p] = 0ull; t1[p] = 0ull; }

#pragma unroll 2
    for (int k = 0; k < HID; k++) {
        const ull* hr = (const ull*)(hTw + k * ATS);
        ull h0 = hr[0], h1 = hr[1], h2 = hr[2], h3 = hr[3];
        float u0 = W2s[k * F + lane];
        float u1 = W2s[k * F + lane + 32];
        ull up0 = pack2(u0, u0);
        ull up1 = pack2(u1, u1);
        t0[0] = ffma2(h0, up0, t0[0]);
        t0[1] = ffma2(h1, up0, t0[1]);
        t0[2] = ffma2(h2, up0, t0[2]);
        t0[3] = ffma2(h3, up0, t0[3]);
        t1[0] = ffma2(h0, up1, t1[0]);
        t1[1] = ffma2(h1, up1, t1[1]);
        t1[2] = ffma2(h2, up1, t1[2]);
        t1[3] = ffma2(h3, up1, t1[3]);
    }

    // ts = t * dinv -> g_ts
#pragma unroll
    for (int p = 0; p < 4; p++) {
        int n0 = nbase + 2 * p;
        int n1 = n0 + 1;
        float lo0, hi0, lo1, hi1;
        unpack2(t0[p], lo0, hi0);
        unpack2(t1[p], lo1, hi1);
        if (n0 < n) {
            float dv = g_dinv[n0];
            g_ts[(size_t)n0 * F + lane] = lo0 * dv;
            g_ts[(size_t)n0 * F + 32 + lane] = lo1 * dv;
        }
        if (n1 < n) {
            float dv = g_dinv[n1];
            g_ts[(size_t)n1 * F + lane] = hi0 * dv;
            g_ts[(size_t)n1 * F + 32 + lane] = hi1 * dv;
        }
    }
}

// ---------------------------------------------------------------- launch
extern "C" void kernel_launch(void* const* d_in, const int* in_sizes, int n_in,
                              void* d_out, int out_size) {
    const float* x  = (const float*)d_in[0];
    const int* ei   = (const int*)d_in[1];   // int32 edge_index [2, E]
    const float* W1 = (const float*)d_in[2];
    const float* b1 = (const float*)d_in[3];
    const float* W2 = (const float*)d_in[4];
    const float* b2 = (const float*)d_in[5];
    float* out      = (float*)d_out;

    int n = in_sizes[0] / F;   // 100000
    int E = in_sizes[1] / 2;   // 1600000
    const int* src = ei;
    const int* dst = ei + E;

    cudaFuncSetAttribute(k_fused, cudaFuncAttributeMaxDynamicSharedMemorySize,
                         FG_BYTES);

    int nbN = (n + 255) / 256;
    int nbE = (E + 255) / 256;

    // CSR build
    k_zero<<<nbN, 256>>>(n);
    k_hist<<<nbE, 256>>>(dst, E);
    k_alloc<<<nbN, 256>>>(n);
    k_permute<<<(E / 2 + 255) / 256, 256>>>(src, dst, E);

    // layer 1 aggregation (reads x, scales by dinv[s] on the fly)
    int gth_blocks = (n * 32 + 255) / 256;
    k_gather<0><<<gth_blocks, 256>>>(x, nullptr, nullptr, n);

    // fused double GEMM
    int fg_blocks = ((n + 7) / 8 + FG_WARPS - 1) / FG_WARPS;
    k_fused<<<fg_blocks, FG_THREADS, FG_BYTES>>>(W1, b1, W2, n);

    // layer 2 aggregation + epilogue
    k_gather<1><<<gth_blocks, 256>>>(nullptr, b2, out, n);
}

// round 9
// speedup vs baseline: 1.2574x; 1.0298x over previous
#include <cuda_runtime.h>
#include <cuda_fp16.h>

// GCN 2-layer, CSR-gather aggregation, FFMA2 double-GEMM, fp16 gather payloads:
//   count = indegree;  dinv = rsqrt(1+count);  CSR rows via warp-aggregated
//   atomicAdd allocation (row order irrelevant, only contiguity needed)
//   xh   = fp16(x * dinv)                                  (k_prep)
//   a    = (sum_{s in N(d)+self} xh[s]) * dinv[d]          (gather1 -> g_agg, fp32)
//   h1   = relu(a @ W1 + b1)   }  fused FFMA2 GEMM kernel
//   tsh  = fp16((h1 @ W2) * dinv)  -> g_tsh
//   out  = (sum tsh[s incl self]) * dinv[d] + b2           (gather2 -> out, fp32)
// All arithmetic fp32; only gathered payloads are fp16 (halves L2 traffic).
// edge_index int32.  Device symbols touched ONLY from device code (GB300 ATS
// makes host-side symbol addresses silently read host memory).

#define NMAX 100000
#define EMAX 1600000
#define F 64
#define HID 128

typedef unsigned long long ull;

__device__ float g_dinv[NMAX];
__device__ __half g_xh[NMAX * F];    // fp16 pre-scaled x
__device__ float g_agg[NMAX * F];    // fp32 GEMM input
__device__ __half g_tsh[NMAX * F];   // fp16 pre-scaled layer-2 activations

__device__ int g_count[NMAX];
__device__ int g_row_start[NMAX];
__device__ int g_cursor[NMAX];
__device__ int g_csr[EMAX];
__device__ int g_total;

// ---------------------------------------------------------------- f32x2 helpers
__device__ __forceinline__ ull pack2(float lo, float hi) {
    ull r;
    asm("mov.b64 %0, {%1, %2};" : "=l"(r) : "f"(lo), "f"(hi));
    return r;
}
__device__ __forceinline__ void unpack2(ull v, float& lo, float& hi) {
    asm("mov.b64 {%0, %1}, %2;" : "=f"(lo), "=f"(hi) : "l"(v));
}
__device__ __forceinline__ ull ffma2(ull a, ull b, ull c) {
    ull d;
    asm("fma.rn.f32x2 %0, %1, %2, %3;" : "=l"(d) : "l"(a), "l"(b), "l"(c));
    return d;
}

// ---------------------------------------------------------------- CSR build
__global__ void k_zero(int n) {
    int i = blockIdx.x * blockDim.x + threadIdx.x;
    if (i == 0) g_total = 0;
    if (i < n) g_count[i] = 0;
}

__global__ void k_hist(const int* __restrict__ dst, int E) {
    int i = blockIdx.x * blockDim.x + threadIdx.x;
    if (i < E) atomicAdd(&g_count[__ldg(&dst[i])], 1);
}

// Row allocation: warp-inclusive scan + one atomicAdd per warp; dinv fused.
__global__ void k_alloc(int n) {
    int i = blockIdx.x * blockDim.x + threadIdx.x;
    int lane = threadIdx.x & 31;
    int cnt = (i < n) ? g_count[i] : 0;
    int sum = cnt;
#pragma unroll
    for (int off = 1; off < 32; off <<= 1) {
        int v = __shfl_up_sync(0xffffffffu, sum, off);
        if (lane >= off) sum += v;
    }
    int total = __shfl_sync(0xffffffffu, sum, 31);
    int base = 0;
    if (lane == 0) base = atomicAdd(&g_total, total);
    base = __shfl_sync(0xffffffffu, base, 0);
    int start = base + sum - cnt;
    if (i < n) {
        g_row_start[i] = start;
        g_cursor[i] = start;
        g_dinv[i] = rsqrtf(1.0f + (float)cnt);
    }
}

__global__ void k_permute(const int* __restrict__ src,
                          const int* __restrict__ dst, int E) {
    int i = (blockIdx.x * blockDim.x + threadIdx.x) * 2;
    if (i + 1 < E) {
        int d0 = __ldg(&dst[i]);
        int d1 = __ldg(&dst[i + 1]);
        int s0 = __ldg(&src[i]);
        int s1 = __ldg(&src[i + 1]);
        int p0 = atomicAdd(&g_cursor[d0], 1);
        int p1 = atomicAdd(&g_cursor[d1], 1);
        g_csr[p0] = s0;
        g_csr[p1] = s1;
    } else if (i < E) {
        int p = atomicAdd(&g_cursor[__ldg(&dst[i])], 1);
        g_csr[p] = __ldg(&src[i]);
    }
}

// ---------------------------------------------------------------- prep
// xh = fp16(x * dinv[row]).  Thread: one 16B fp32 chunk -> 8B fp16 chunk.
__global__ void k_prep(const float* __restrict__ x, int n) {
    int i = blockIdx.x * blockDim.x + threadIdx.x;
    if (i >= n * 16) return;
    int node = i >> 4;
    float dv = g_dinv[node];
    float4 v = ((const float4*)x)[i];
    __half2 h0 = __floats2half2_rn(v.x * dv, v.y * dv);
    __half2 h1 = __floats2half2_rn(v.z * dv, v.w * dv);
    uint2 o;
    *(__half2*)&o.x = h0;
    *(__half2*)&o.y = h1;
    ((uint2*)g_xh)[i] = o;
}

// ---------------------------------------------------------------- gathers
// One warp per dst node. 16 lanes x 8B chunk (4 fp16 features); lanes 0-15
// even edges, 16-31 odd edges; merged via shfl_down(16). fp32 accumulation.
// MODE 0: source g_xh (pre-scaled) -> acc*dinv[d] -> g_agg (fp32)
// MODE 1: source g_tsh (pre-scaled) -> acc*dinv[d] + b2 -> out (fp32)
template <int MODE>
__global__ void __launch_bounds__(256)
k_gather(const float* __restrict__ b2, float* __restrict__ outparam, int n) {
    int gwarp = (blockIdx.x * blockDim.x + threadIdx.x) >> 5;
    if (gwarp >= n) return;
    int lane = threadIdx.x & 31;
    int d = gwarp;
    int c = lane & 15;
    int half = lane >> 4;

    const uint2* bh = (MODE == 0) ? (const uint2*)g_xh : (const uint2*)g_tsh;
    float4 acc = make_float4(0.f, 0.f, 0.f, 0.f);

    int start = g_row_start[d];
    int end = start + g_count[d];
    int e = start + half;
    for (; e + 2 < end; e += 4) {
        int s0 = __ldg(&g_csr[e]);
        int s1 = __ldg(&g_csr[e + 2]);
        uint2 r0 = bh[(size_t)s0 * 16 + c];
        uint2 r1 = bh[(size_t)s1 * 16 + c];
        float2 p0 = __half22float2(*(__half2*)&r0.x);
        float2 p1 = __half22float2(*(__half2*)&r0.y);
        float2 q0 = __half22float2(*(__half2*)&r1.x);
        float2 q1 = __half22float2(*(__half2*)&r1.y);
        acc.x += p0.x + q0.x;
        acc.y += p0.y + q0.y;
        acc.z += p1.x + q1.x;
        acc.w += p1.y + q1.y;
    }
    if (e < end) {
        int s = __ldg(&g_csr[e]);
        uint2 r = bh[(size_t)s * 16 + c];
        float2 p0 = __half22float2(*(__half2*)&r.x);
        float2 p1 = __half22float2(*(__half2*)&r.y);
        acc.x += p0.x; acc.y += p0.y; acc.z += p1.x; acc.w += p1.y;
    }

    acc.x += __shfl_down_sync(0xffffffffu, acc.x, 16);
    acc.y += __shfl_down_sync(0xffffffffu, acc.y, 16);
    acc.z += __shfl_down_sync(0xffffffffu, acc.z, 16);
    acc.w += __shfl_down_sync(0xffffffffu, acc.w, 16);

    if (half == 0) {
        uint2 sv = bh[(size_t)d * 16 + c];
        float2 s0 = __half22float2(*(__half2*)&sv.x);
        float2 s1 = __half22float2(*(__half2*)&sv.y);
        acc.x += s0.x; acc.y += s0.y; acc.z += s1.x; acc.w += s1.y;
        float dvd = g_dinv[d];
        acc.x *= dvd; acc.y *= dvd; acc.z *= dvd; acc.w *= dvd;
        if (MODE == 1) {
            float4 bb = ((const float4*)b2)[c];
            acc.x += bb.x; acc.y += bb.y; acc.z += bb.z; acc.w += bb.w;
        }
        float4* dst4 = (MODE == 0) ? (float4*)g_agg : (float4*)outparam;
        dst4[(size_t)d * 16 + c] = acc;
    }
}

// ---------------------------------------------------------------- fused GEMMs
// Warp handles 8 nodes.  acc pairs adjacent nodes -> fma.rn.f32x2.
#define FG_WARPS 6
#define FG_THREADS (FG_WARPS * 32)
#define ATS 10
#define OFF_W2 8192
#define OFF_B1 16384
#define OFF_AT 16512
#define OFF_HT (OFF_AT + FG_WARPS * (F * ATS))
#define FG_FLOATS (OFF_HT + FG_WARPS * (HID * ATS))
#define FG_BYTES (FG_FLOATS * 4)

__global__ void __launch_bounds__(FG_THREADS, 2)
k_fused(const float* __restrict__ W1, const float* __restrict__ b1,
        const float* __restrict__ W2, int n) {
    extern __shared__ float smem[];
    float* W1s = smem;
    float* W2s = smem + OFF_W2;
    float* b1s = smem + OFF_B1;
    int tid = threadIdx.x;
    int warp = tid >> 5;
    int lane = tid & 31;

    for (int j = tid; j < (F * HID) / 4; j += FG_THREADS)
        ((float4*)W1s)[j] = ((const float4*)W1)[j];
    for (int j = tid; j < (HID * F) / 4; j += FG_THREADS)
        ((float4*)W2s)[j] = ((const float4*)W2)[j];
    for (int j = tid; j < HID; j += FG_THREADS) b1s[j] = b1[j];
    __syncthreads();

    int nbase = (blockIdx.x * FG_WARPS + warp) * 8;
    if (nbase >= n) return;
    float* aTw = smem + OFF_AT + warp * (F * ATS);
    float* hTw = smem + OFF_HT + warp * (HID * ATS);

#pragma unroll
    for (int ni = 0; ni < 8; ni++) {
        int node = nbase + ni;
        float a0 = 0.f, a1 = 0.f;
        if (node < n) {
            a0 = g_agg[(size_t)node * F + lane];
            a1 = g_agg[(size_t)node * F + 32 + lane];
        }
        aTw[lane * ATS + ni] = a0;
        aTw[(lane + 32) * ATS + ni] = a1;
    }
    __syncwarp();

    // ---- layer 1
    ull acc1[4][4];
#pragma unroll
    for (int p = 0; p < 4; p++)
#pragma unroll
        for (int j = 0; j < 4; j++) acc1[p][j] = 0ull;

#pragma unroll 4
    for (int k = 0; k < F; k++) {
        const ull* ar = (const ull*)(aTw + k * ATS);
        ull a0 = ar[0], a1 = ar[1], a2 = ar[2], a3 = ar[3];
        const float* wr = W1s + k * HID + lane;
        ull w0 = pack2(wr[0], wr[0]);
        ull w1 = pack2(wr[32], wr[32]);
        ull w2 = pack2(wr[64], wr[64]);
        ull w3 = pack2(wr[96], wr[96]);
        acc1[0][0] = ffma2(a0, w0, acc1[0][0]);
        acc1[0][1] = ffma2(a0, w1, acc1[0][1]);
        acc1[0][2] = ffma2(a0, w2, acc1[0][2]);
        acc1[0][3] = ffma2(a0, w3, acc1[0][3]);
        acc1[1][0] = ffma2(a1, w0, acc1[1][0]);
        acc1[1][1] = ffma2(a1, w1, acc1[1][1]);
        acc1[1][2] = ffma2(a1, w2, acc1[1][2]);
        acc1[1][3] = ffma2(a1, w3, acc1[1][3]);
        acc1[2][0] = ffma2(a2, w0, acc1[2][0]);
        acc1[2][1] = ffma2(a2, w1, acc1[2][1]);
        acc1[2][2] = ffma2(a2, w2, acc1[2][2]);
        acc1[2][3] = ffma2(a2, w3, acc1[2][3]);
        acc1[3][0] = ffma2(a3, w0, acc1[3][0]);
        acc1[3][1] = ffma2(a3, w1, acc1[3][1]);
        acc1[3][2] = ffma2(a3, w2, acc1[3][2]);
        acc1[3][3] = ffma2(a3, w3, acc1[3][3]);
    }

    // bias + relu -> hT
#pragma unroll
    for (int j = 0; j < 4; j++) {
        float bb = b1s[lane + 32 * j];
        float* hrow = hTw + (lane + 32 * j) * ATS;
#pragma unroll
        for (int p = 0; p < 4; p++) {
            float lo, hi;
            unpack2(acc1[p][j], lo, hi);
            lo = fmaxf(lo + bb, 0.f);
            hi = fmaxf(hi + bb, 0.f);
            ((ull*)hrow)[p] = pack2(lo, hi);
        }
    }
    __syncwarp();

    // ---- layer 2
    ull t0[4], t1[4];
#pragma unroll
    for (int p = 0; p < 4; p++) { t0[p] = 0ull; t1[p] = 0ull; }

#pragma unroll 2
    for (int k = 0; k < HID; k++) {
        const ull* hr = (const ull*)(hTw + k * ATS);
        ull h0 = hr[0], h1 = hr[1], h2 = hr[2], h3 = hr[3];
        float u0 = W2s[k * F + lane];
        float u1 = W2s[k * F + lane + 32];
        ull up0 = pack2(u0, u0);
        ull up1 = pack2(u1, u1);
        t0[0] = ffma2(h0, up0, t0[0]);
        t0[1] = ffma2(h1, up0, t0[1]);
        t0[2] = ffma2(h2, up0, t0[2]);
        t0[3] = ffma2(h3, up0, t0[3]);
        t1[0] = ffma2(h0, up1, t1[0]);
        t1[1] = ffma2(h1, up1, t1[1]);
        t1[2] = ffma2(h2, up1, t1[2]);
        t1[3] = ffma2(h3, up1, t1[3]);
    }

    // tsh = fp16(t * dinv) -> g_tsh
#pragma unroll
    for (int p = 0; p < 4; p++) {
        int n0 = nbase + 2 * p;
        int n1 = n0 + 1;
        float lo0, hi0, lo1, hi1;
        unpack2(t0[p], lo0, hi0);
        unpack2(t1[p], lo1, hi1);
        if (n0 < n) {
            float dv = g_dinv[n0];
            g_tsh[(size_t)n0 * F + lane] = __float2half_rn(lo0 * dv);
            g_tsh[(size_t)n0 * F + 32 + lane] = __float2half_rn(lo1 * dv);
        }
        if (n1 < n) {
            float dv = g_dinv[n1];
            g_tsh[(size_t)n1 * F + lane] = __float2half_rn(hi0 * dv);
            g_tsh[(size_t)n1 * F + 32 + lane] = __float2half_rn(hi1 * dv);
        }
    }
}

// ---------------------------------------------------------------- launch
extern "C" void kernel_launch(void* const* d_in, const int* in_sizes, int n_in,
                              void* d_out, int out_size) {
    const float* x  = (const float*)d_in[0];
    const int* ei   = (const int*)d_in[1];   // int32 edge_index [2, E]
    const float* W1 = (const float*)d_in[2];
    const float* b1 = (const float*)d_in[3];
    const float* W2 = (const float*)d_in[4];
    const float* b2 = (const float*)d_in[5];
    float* out      = (float*)d_out;

    int n = in_sizes[0] / F;   // 100000
    int E = in_sizes[1] / 2;   // 1600000
    const int* src = ei;
    const int* dst = ei + E;

    cudaFuncSetAttribute(k_fused, cudaFuncAttributeMaxDynamicSharedMemorySize,
                         FG_BYTES);

    int nbN = (n + 255) / 256;
    int nbE = (E + 255) / 256;

    // CSR build
    k_zero<<<nbN, 256>>>(n);
    k_hist<<<nbE, 256>>>(dst, E);
    k_alloc<<<nbN, 256>>>(n);
    k_permute<<<(E / 2 + 255) / 256, 256>>>(src, dst, E);

    // fp16 pre-scaled features
    k_prep<<<(n * 16 + 255) / 256, 256>>>(x, n);

    // layer 1 aggregation
    int gth_blocks = (n * 32 + 255) / 256;
    k_gather<0><<<gth_blocks, 256>>>(nullptr, nullptr, n);

    // fused double GEMM
    int fg_blocks = ((n + 7) / 8 + FG_WARPS - 1) / FG_WARPS;
    k_fused<<<fg_blocks, FG_THREADS, FG_BYTES>>>(W1, b1, W2, n);

    // layer 2 aggregation + epilogue
    k_gather<1><<<gth_blocks, 256>>>(b2, out, n);
}

// round 10
// speedup vs baseline: 1.2604x; 1.0024x over previous
#include <cuda_runtime.h>
#include <cuda_fp16.h>

// GCN 2-layer, CSR-gather aggregation, FFMA2 double-GEMM, fp16 gather payloads.
// Gather uses 4 edge-groups/warp (8 lanes x 16B fp16 = one 128B row per group)
// with 2-deep unroll -> 8 edges in flight per warp (latency-bound fix).
//   count = indegree;  dinv = rsqrt(1+count);  CSR rows via warp-aggregated
//   atomicAdd allocation (row order irrelevant, only contiguity needed)
//   xh   = fp16(x * dinv)                                  (k_prep)
//   a    = (sum_{s in N(d)+self} xh[s]) * dinv[d]          (gather1 -> g_agg)
//   h1   = relu(a @ W1 + b1)   }  fused FFMA2 GEMM kernel
//   tsh  = fp16((h1 @ W2) * dinv)  -> g_tsh
//   out  = (sum tsh[s incl self]) * dinv[d] + b2           (gather2 -> out)
// edge_index int32.  Device symbols touched ONLY from device code (GB300 ATS
// makes host-side symbol addresses silently read host memory).

#define NMAX 100000
#define EMAX 1600000
#define F 64
#define HID 128

typedef unsigned long long ull;

__device__ float g_dinv[NMAX];
__device__ __half g_xh[NMAX * F];    // fp16 pre-scaled x
__device__ float g_agg[NMAX * F];    // fp32 GEMM input
__device__ __half g_tsh[NMAX * F];   // fp16 pre-scaled layer-2 activations

__device__ int g_count[NMAX];
__device__ int g_row_start[NMAX];
__device__ int g_cursor[NMAX];
__device__ int g_csr[EMAX];
__device__ int g_total;

// ---------------------------------------------------------------- f32x2 helpers
__device__ __forceinline__ ull pack2(float lo, float hi) {
    ull r;
    asm("mov.b64 %0, {%1, %2};" : "=l"(r) : "f"(lo), "f"(hi));
    return r;
}
__device__ __forceinline__ void unpack2(ull v, float& lo, float& hi) {
    asm("mov.b64 {%0, %1}, %2;" : "=f"(lo), "=f"(hi) : "l"(v));
}
__device__ __forceinline__ ull ffma2(ull a, ull b, ull c) {
    ull d;
    asm("fma.rn.f32x2 %0, %1, %2, %3;" : "=l"(d) : "l"(a), "l"(b), "l"(c));
    return d;
}

// ---------------------------------------------------------------- CSR build
__global__ void k_zero(int n) {
    int i = blockIdx.x * blockDim.x + threadIdx.x;
    if (i == 0) g_total = 0;
    if (i < n) g_count[i] = 0;
}

__global__ void k_hist(const int* __restrict__ dst, int E) {
    int i = blockIdx.x * blockDim.x + threadIdx.x;
    if (i < E) atomicAdd(&g_count[__ldg(&dst[i])], 1);
}

// Row allocation: warp-inclusive scan + one atomicAdd per warp; dinv fused.
__global__ void k_alloc(int n) {
    int i = blockIdx.x * blockDim.x + threadIdx.x;
    int lane = threadIdx.x & 31;
    int cnt = (i < n) ? g_count[i] : 0;
    int sum = cnt;
#pragma unroll
    for (int off = 1; off < 32; off <<= 1) {
        int v = __shfl_up_sync(0xffffffffu, sum, off);
        if (lane >= off) sum += v;
    }
    int total = __shfl_sync(0xffffffffu, sum, 31);
    int base = 0;
    if (lane == 0) base = atomicAdd(&g_total, total);
    base = __shfl_sync(0xffffffffu, base, 0);
    int start = base + sum - cnt;
    if (i < n) {
        g_row_start[i] = start;
        g_cursor[i] = start;
        g_dinv[i] = rsqrtf(1.0f + (float)cnt);
    }
}

__global__ void k_permute(const int* __restrict__ src,
                          const int* __restrict__ dst, int E) {
    int i = (blockIdx.x * blockDim.x + threadIdx.x) * 2;
    if (i + 1 < E) {
        int d0 = __ldg(&dst[i]);
        int d1 = __ldg(&dst[i + 1]);
        int s0 = __ldg(&src[i]);
        int s1 = __ldg(&src[i + 1]);
        int p0 = atomicAdd(&g_cursor[d0], 1);
        int p1 = atomicAdd(&g_cursor[d1], 1);
        g_csr[p0] = s0;
        g_csr[p1] = s1;
    } else if (i < E) {
        int p = atomicAdd(&g_cursor[__ldg(&dst[i])], 1);
        g_csr[p] = __ldg(&src[i]);
    }
}

// ---------------------------------------------------------------- prep
// xh = fp16(x * dinv[row]).  Thread: one 16B fp32 chunk -> 8B fp16 chunk.
__global__ void k_prep(const float* __restrict__ x, int n) {
    int i = blockIdx.x * blockDim.x + threadIdx.x;
    if (i >= n * 16) return;
    int node = i >> 4;
    float dv = g_dinv[node];
    float4 v = ((const float4*)x)[i];
    __half2 h0 = __floats2half2_rn(v.x * dv, v.y * dv);
    __half2 h1 = __floats2half2_rn(v.z * dv, v.w * dv);
    uint2 o;
    *(__half2*)&o.x = h0;
    *(__half2*)&o.y = h1;
    ((uint2*)g_xh)[i] = o;
}

// ---------------------------------------------------------------- gathers
// One warp per dst node.  4 groups of 8 lanes; group g handles edges
// start+g, start+g+4, ...; each lane loads uint4 (16B = 8 fp16 feats).
// 2-deep unroll -> 8 edges in flight per warp.  Groups merged via
// shfl_down(16)+shfl_down(8); lanes 0-7 write fp32 output (2x float4).
// MODE 0: source g_xh -> acc*dinv[d] -> g_agg
// MODE 1: source g_tsh -> acc*dinv[d] + b2 -> out
__device__ __forceinline__ void acc_row(float* acc, uint4 r) {
    float2 p0 = __half22float2(*(__half2*)&r.x);
    float2 p1 = __half22float2(*(__half2*)&r.y);
    float2 p2 = __half22float2(*(__half2*)&r.z);
    float2 p3 = __half22float2(*(__half2*)&r.w);
    acc[0] += p0.x; acc[1] += p0.y;
    acc[2] += p1.x; acc[3] += p1.y;
    acc[4] += p2.x; acc[5] += p2.y;
    acc[6] += p3.x; acc[7] += p3.y;
}

template <int MODE>
__global__ void __launch_bounds__(256)
k_gather(const float* __restrict__ b2, float* __restrict__ outparam, int n) {
    int gwarp = (blockIdx.x * blockDim.x + threadIdx.x) >> 5;
    if (gwarp >= n) return;
    int lane = threadIdx.x & 31;
    int d = gwarp;
    int g = lane >> 3;     // edge group 0-3
    int t = lane & 7;      // 16B chunk within row

    const uint4* bh = (MODE == 0) ? (const uint4*)g_xh : (const uint4*)g_tsh;
    float acc[8];
#pragma unroll
    for (int q = 0; q < 8; q++) acc[q] = 0.f;

    int start = g_row_start[d];
    int end = start + g_count[d];
    int e = start + g;
    for (; e + 4 < end; e += 8) {
        int s0 = __ldg(&g_csr[e]);
        int s1 = __ldg(&g_csr[e + 4]);
        uint4 r0 = bh[(size_t)s0 * 8 + t];
        uint4 r1 = bh[(size_t)s1 * 8 + t];
        acc_row(acc, r0);
        acc_row(acc, r1);
    }
    if (e < end) {
        int s = __ldg(&g_csr[e]);
        uint4 r = bh[(size_t)s * 8 + t];
        acc_row(acc, r);
    }

    // merge 4 groups
#pragma unroll
    for (int q = 0; q < 8; q++) {
        acc[q] += __shfl_down_sync(0xffffffffu, acc[q], 16);
        acc[q] += __shfl_down_sync(0xffffffffu, acc[q], 8);
    }

    if (g == 0) {
        // self loop
        uint4 sv = bh[(size_t)d * 8 + t];
        acc_row(acc, sv);
        float dvd = g_dinv[d];
#pragma unroll
        for (int q = 0; q < 8; q++) acc[q] *= dvd;
        float4* dst4 = (MODE == 0) ? (float4*)g_agg : (float4*)outparam;
        float4 o0 = make_float4(acc[0], acc[1], acc[2], acc[3]);
        float4 o1 = make_float4(acc[4], acc[5], acc[6], acc[7]);
        if (MODE == 1) {
            float4 bb0 = ((const float4*)b2)[t * 2];
            float4 bb1 = ((const float4*)b2)[t * 2 + 1];
            o0.x += bb0.x; o0.y += bb0.y; o0.z += bb0.z; o0.w += bb0.w;
            o1.x += bb1.x; o1.y += bb1.y; o1.z += bb1.z; o1.w += bb1.w;
        }
        dst4[(size_t)d * 16 + t * 2] = o0;
        dst4[(size_t)d * 16 + t * 2 + 1] = o1;
    }
}

// ---------------------------------------------------------------- fused GEMMs
// Warp handles 8 nodes.  acc pairs adjacent nodes -> fma.rn.f32x2.
#define FG_WARPS 6
#define FG_THREADS (FG_WARPS * 32)
#define ATS 10
#define OFF_W2 8192
#define OFF_B1 16384
#define OFF_AT 16512
#define OFF_HT (OFF_AT + FG_WARPS * (F * ATS))
#define FG_FLOATS (OFF_HT + FG_WARPS * (HID * ATS))
#define FG_BYTES (FG_FLOATS * 4)

__global__ void __launch_bounds__(FG_THREADS, 2)
k_fused(const float* __restrict__ W1, const float* __restrict__ b1,
        const float* __restrict__ W2, int n) {
    extern __shared__ float smem[];
    float* W1s = smem;
    float* W2s = smem + OFF_W2;
    float* b1s = smem + OFF_B1;
    int tid = threadIdx.x;
    int warp = tid >> 5;
    int lane = tid & 31;

    for (int j = tid; j < (F * HID) / 4; j += FG_THREADS)
        ((float4*)W1s)[j] = ((const float4*)W1)[j];
    for (int j = tid; j < (HID * F) / 4; j += FG_THREADS)
        ((float4*)W2s)[j] = ((const float4*)W2)[j];
    for (int j = tid; j < HID; j += FG_THREADS) b1s[j] = b1[j];
    __syncthreads();

    int nbase = (blockIdx.x * FG_WARPS + warp) * 8;
    if (nbase >= n) return;
    float* aTw = smem + OFF_AT + warp * (F * ATS);
    float* hTw = smem + OFF_HT + warp * (HID * ATS);

#pragma unroll
    for (int ni = 0; ni < 8; ni++) {
        int node = nbase + ni;
        float a0 = 0.f, a1 = 0.f;
        if (node < n) {
            a0 = g_agg[(size_t)node * F + lane];
            a1 = g_agg[(size_t)node * F + 32 + lane];
        }
        aTw[lane * ATS + ni] = a0;
        aTw[(lane + 32) * ATS + ni] = a1;
    }
    __syncwarp();

    // ---- layer 1
    ull acc1[4][4];
#pragma unroll
    for (int p = 0; p < 4; p++)
#pragma unroll
        for (int j = 0; j < 4; j++) acc1[p][j] = 0ull;

#pragma unroll 4
    for (int k = 0; k < F; k++) {
        const ull* ar = (const ull*)(aTw + k * ATS);
        ull a0 = ar[0], a1 = ar[1], a2 = ar[2], a3 = ar[3];
        const float* wr = W1s + k * HID + lane;
        ull w0 = pack2(wr[0], wr[0]);
        ull w1 = pack2(wr[32], wr[32]);
        ull w2 = pack2(wr[64], wr[64]);
        ull w3 = pack2(wr[96], wr[96]);
        acc1[0][0] = ffma2(a0, w0, acc1[0][0]);
        acc1[0][1] = ffma2(a0, w1, acc1[0][1]);
        acc1[0][2] = ffma2(a0, w2, acc1[0][2]);
        acc1[0][3] = ffma2(a0, w3, acc1[0][3]);
        acc1[1][0] = ffma2(a1, w0, acc1[1][0]);
        acc1[1][1] = ffma2(a1, w1, acc1[1][1]);
        acc1[1][2] = ffma2(a1, w2, acc1[1][2]);
        acc1[1][3] = ffma2(a1, w3, acc1[1][3]);
        acc1[2][0] = ffma2(a2, w0, acc1[2][0]);
        acc1[2][1] = ffma2(a2, w1, acc1[2][1]);
        acc1[2][2] = ffma2(a2, w2, acc1[2][2]);
        acc1[2][3] = ffma2(a2, w3, acc1[2][3]);
        acc1[3][0] = ffma2(a3, w0, acc1[3][0]);
        acc1[3][1] = ffma2(a3, w1, acc1[3][1]);
        acc1[3][2] = ffma2(a3, w2, acc1[3][2]);
        acc1[3][3] = ffma2(a3, w3, acc1[3][3]);
    }

    // bias + relu -> hT
#pragma unroll
    for (int j = 0; j < 4; j++) {
        float bb = b1s[lane + 32 * j];
        float* hrow = hTw + (lane + 32 * j) * ATS;
#pragma unroll
        for (int p = 0; p < 4; p++) {
            float lo, hi;
            unpack2(acc1[p][j], lo, hi);
            lo = fmaxf(lo + bb, 0.f);
            hi = fmaxf(hi + bb, 0.f);
            ((ull*)hrow)[p] = pack2(lo, hi);
        }
    }
    __syncwarp();

    // ---- layer 2
    ull t0[4], t1[4];
#pragma unroll
    for (int p = 0; p < 4; p++) { t0[p] = 0ull; t1[p] = 0ull; }

#pragma unroll 2
    for (int k = 0; k < HID; k++) {
        const ull* hr = (const ull*)(hTw + k * ATS);
        ull h0 = hr[0], h1 = hr[1], h2 = hr[2], h3 = hr[3];
        float u0 = W2s[k * F + lane];
        float u1 = W2s[k * F + lane + 32];
        ull up0 = pack2(u0, u0);
        ull up1 = pack2(u1, u1);
        t0[0] = ffma2(h0, up0, t0[0]);
        t0[1] = ffma2(h1, up0, t0[1]);
        t0[2] = ffma2(h2, up0, t0[2]);
        t0[3] = ffma2(h3, up0, t0[3]);
        t1[0] = ffma2(h0, up1, t1[0]);
        t1[1] = ffma2(h1, up1, t1[1]);
        t1[2] = ffma2(h2, up1, t1[2]);
        t1[3] = ffma2(h3, up1, t1[3]);
    }

    // tsh = fp16(t * dinv) -> g_tsh
#pragma unroll
    for (int p = 0; p < 4; p++) {
        int n0 = nbase + 2 * p;
        int n1 = n0 + 1;
        float lo0, hi0, lo1, hi1;
        unpack2(t0[p], lo0, hi0);
        unpack2(t1[p], lo1, hi1);
        if (n0 < n) {
            float dv = g_dinv[n0];
            g_tsh[(size_t)n0 * F + lane] = __float2half_rn(lo0 * dv);
            g_tsh[(size_t)n0 * F + 32 + lane] = __float2half_rn(lo1 * dv);
        }
        if (n1 < n) {
            float dv = g_dinv[n1];
            g_tsh[(size_t)n1 * F + lane] = __float2half_rn(hi0 * dv);
            g_tsh[(size_t)n1 * F + 32 + lane] = __float2half_rn(hi1 * dv);
        }
    }
}

// ---------------------------------------------------------------- launch
extern "C" void kernel_launch(void* const* d_in, const int* in_sizes, int n_in,
                              void* d_out, int out_size) {
    const float* x  = (const float*)d_in[0];
    const int* ei   = (const int*)d_in[1];   // int32 edge_index [2, E]
    const float* W1 = (const float*)d_in[2];
    const float* b1 = (const float*)d_in[3];
    const float* W2 = (const float*)d_in[4];
    const float* b2 = (const float*)d_in[5];
    float* out      = (float*)d_out;

    int n = in_sizes[0] / F;   // 100000
    int E = in_sizes[1] / 2;   // 1600000
    const int* src = ei;
    const int* dst = ei + E;

    cudaFuncSetAttribute(k_fused, cudaFuncAttributeMaxDynamicSharedMemorySize,
                         FG_BYTES);

    int nbN = (n + 255) / 256;
    int nbE = (E + 255) / 256;

    // CSR build
    k_zero<<<nbN, 256>>>(n);
    k_hist<<<nbE, 256>>>(dst, E);
    k_alloc<<<nbN, 256>>>(n);
    k_permute<<<(E / 2 + 255) / 256, 256>>>(src, dst, E);

    // fp16 pre-scaled features
    k_prep<<<(n * 16 + 255) / 256, 256>>>(x, n);

    // layer 1 aggregation
    int gth_blocks = (n * 32 + 255) / 256;
    k_gather<0><<<gth_blocks, 256>>>(nullptr, nullptr, n);

    // fused double GEMM
    int fg_blocks = ((n + 7) / 8 + FG_WARPS - 1) / FG_WARPS;
    k_fused<<<fg_blocks, FG_THREADS, FG_BYTES>>>(W1, b1, W2, n);

    // layer 2 aggregation + epilogue
    k_gather<1><<<gth_blocks, 256>>>(b2, out, n);
}

// round 11
// speedup vs baseline: 1.2816x; 1.0168x over previous
#include <cuda_runtime.h>
#include <cuda_fp16.h>

// GCN 2-layer, CSR-gather aggregation, FFMA2 double-GEMM, fp16 gather payloads.
//   count = indegree;  dinv = rsqrt(1+count);  CSR rows via warp-aggregated
//   atomicAdd allocation;  xh = fp16(x*dinv) fused into k_alloc.
//   a    = (sum_{s in N(d)+self} xh[s]) * dinv[d]          (gather1 -> g_agg)
//   h1   = relu(a @ W1 + b1)   }  fused FFMA2 GEMM kernel (ATS=8, LDS.128)
//   tsh  = fp16((h1 @ W2) * dinv)  -> g_tsh
//   out  = (sum tsh[s incl self]) * dinv[d] + b2           (gather2 -> out)
// edge_index int32.  Device symbols touched ONLY from device code (GB300 ATS
// makes host-side symbol addresses silently read host memory).

#define NMAX 100000
#define EMAX 1600000
#define F 64
#define HID 128

typedef unsigned long long ull;

__device__ float g_dinv[NMAX];
__device__ __half g_xh[NMAX * F];    // fp16 pre-scaled x
__device__ float g_agg[NMAX * F];    // fp32 GEMM input
__device__ __half g_tsh[NMAX * F];   // fp16 pre-scaled layer-2 activations

__device__ int g_count[NMAX];
__device__ int g_row_start[NMAX];
__device__ int g_cursor[NMAX];
__device__ int g_csr[EMAX];
__device__ int g_total;

// ---------------------------------------------------------------- f32x2 helpers
__device__ __forceinline__ ull pack2(float lo, float hi) {
    ull r;
    asm("mov.b64 %0, {%1, %2};" : "=l"(r) : "f"(lo), "f"(hi));
    return r;
}
__device__ __forceinline__ void unpack2(ull v, float& lo, float& hi) {
    asm("mov.b64 {%0, %1}, %2;" : "=f"(lo), "=f"(hi) : "l"(v));
}
__device__ __forceinline__ ull ffma2(ull a, ull b, ull c) {
    ull d;
    asm("fma.rn.f32x2 %0, %1, %2, %3;" : "=l"(d) : "l"(a), "l"(b), "l"(c));
    return d;
}

// ---------------------------------------------------------------- CSR build
__global__ void k_zero(int n) {
    int i = blockIdx.x * blockDim.x + threadIdx.x;
    if (i == 0) g_total = 0;
    if (i < n) g_count[i] = 0;
}

__global__ void k_hist(const int* __restrict__ dst, int E) {
    int i = blockIdx.x * blockDim.x + threadIdx.x;
    if (i < E) atomicAdd(&g_count[__ldg(&dst[i])], 1);
}

// Row allocation (warp scan + one atomicAdd per warp) + dinv + fp16 prep.
__global__ void k_alloc(const float* __restrict__ x, int n) {
    int i = blockIdx.x * blockDim.x + threadIdx.x;
    int lane = threadIdx.x & 31;
    int cnt = (i < n) ? g_count[i] : 0;
    int sum = cnt;
#pragma unroll
    for (int off = 1; off < 32; off <<= 1) {
        int v = __shfl_up_sync(0xffffffffu, sum, off);
        if (lane >= off) sum += v;
    }
    int total = __shfl_sync(0xffffffffu, sum, 31);
    int base = 0;
    if (lane == 0) base = atomicAdd(&g_total, total);
    base = __shfl_sync(0xffffffffu, base, 0);
    int start = base + sum - cnt;
    if (i < n) {
        g_row_start[i] = start;
        g_cursor[i] = start;
        float dv = rsqrtf(1.0f + (float)cnt);
        g_dinv[i] = dv;
        // fused prep: xh row = fp16(x row * dv)
        const float4* xr = (const float4*)(x + (size_t)i * F);
        uint2* o = (uint2*)(g_xh + (size_t)i * F);
#pragma unroll
        for (int q = 0; q < 16; q++) {
            float4 v = xr[q];
            __half2 h0 = __floats2half2_rn(v.x * dv, v.y * dv);
            __half2 h1 = __floats2half2_rn(v.z * dv, v.w * dv);
            uint2 u;
            *(__half2*)&u.x = h0;
            *(__half2*)&u.y = h1;
            o[q] = u;
        }
    }
}

__global__ void k_permute(const int* __restrict__ src,
                          const int* __restrict__ dst, int E) {
    int i = (blockIdx.x * blockDim.x + threadIdx.x) * 2;
    if (i + 1 < E) {
        int d0 = __ldg(&dst[i]);
        int d1 = __ldg(&dst[i + 1]);
        int s0 = __ldg(&src[i]);
        int s1 = __ldg(&src[i + 1]);
        int p0 = atomicAdd(&g_cursor[d0], 1);
        int p1 = atomicAdd(&g_cursor[d1], 1);
        g_csr[p0] = s0;
        g_csr[p1] = s1;
    } else if (i < E) {
        int p = atomicAdd(&g_cursor[__ldg(&dst[i])], 1);
        g_csr[p] = __ldg(&src[i]);
    }
}

// ---------------------------------------------------------------- gathers
// One warp per dst node.  4 groups of 8 lanes; each lane loads uint4
// (16B = 8 fp16 feats); 2-deep unroll.  Groups merged via shfl_down.
// MODE 0: source g_xh -> acc*dinv[d] -> g_agg
// MODE 1: source g_tsh -> acc*dinv[d] + b2 -> out
__device__ __forceinline__ void acc_row(float* acc, uint4 r) {
    float2 p0 = __half22float2(*(__half2*)&r.x);
    float2 p1 = __half22float2(*(__half2*)&r.y);
    float2 p2 = __half22float2(*(__half2*)&r.z);
    float2 p3 = __half22float2(*(__half2*)&r.w);
    acc[0] += p0.x; acc[1] += p0.y;
    acc[2] += p1.x; acc[3] += p1.y;
    acc[4] += p2.x; acc[5] += p2.y;
    acc[6] += p3.x; acc[7] += p3.y;
}

template <int MODE>
__global__ void __launch_bounds__(256)
k_gather(const float* __restrict__ b2, float* __restrict__ outparam, int n) {
    int gwarp = (blockIdx.x * blockDim.x + threadIdx.x) >> 5;
    if (gwarp >= n) return;
    int lane = threadIdx.x & 31;
    int d = gwarp;
    int g = lane >> 3;     // edge group 0-3
    int t = lane & 7;      // 16B chunk within row

    const uint4* bh = (MODE == 0) ? (const uint4*)g_xh : (const uint4*)g_tsh;
    float acc[8];
#pragma unroll
    for (int q = 0; q < 8; q++) acc[q] = 0.f;

    int start = g_row_start[d];
    int end = start + g_count[d];
    int e = start + g;
    for (; e + 4 < end; e += 8) {
        int s0 = __ldg(&g_csr[e]);
        int s1 = __ldg(&g_csr[e + 4]);
        uint4 r0 = bh[(size_t)s0 * 8 + t];
        uint4 r1 = bh[(size_t)s1 * 8 + t];
        acc_row(acc, r0);
        acc_row(acc, r1);
    }
    if (e < end) {
        int s = __ldg(&g_csr[e]);
        uint4 r = bh[(size_t)s * 8 + t];
        acc_row(acc, r);
    }

#pragma unroll
    for (int q = 0; q < 8; q++) {
        acc[q] += __shfl_down_sync(0xffffffffu, acc[q], 16);
        acc[q] += __shfl_down_sync(0xffffffffu, acc[q], 8);
    }

    if (g == 0) {
        uint4 sv = bh[(size_t)d * 8 + t];     // self loop
        acc_row(acc, sv);
        float dvd = g_dinv[d];
#pragma unroll
        for (int q = 0; q < 8; q++) acc[q] *= dvd;
        float4* dst4 = (MODE == 0) ? (float4*)g_agg : (float4*)outparam;
        float4 o0 = make_float4(acc[0], acc[1], acc[2], acc[3]);
        float4 o1 = make_float4(acc[4], acc[5], acc[6], acc[7]);
        if (MODE == 1) {
            float4 bb0 = ((const float4*)b2)[t * 2];
            float4 bb1 = ((const float4*)b2)[t * 2 + 1];
            o0.x += bb0.x; o0.y += bb0.y; o0.z += bb0.z; o0.w += bb0.w;
            o1.x += bb1.x; o1.y += bb1.y; o1.z += bb1.z; o1.w += bb1.w;
        }
        dst4[(size_t)d * 16 + t * 2] = o0;
        dst4[(size_t)d * 16 + t * 2 + 1] = o1;
    }
}

// ---------------------------------------------------------------- fused GEMMs
// Warp handles 8 nodes; acc pairs adjacent nodes -> fma.rn.f32x2.
// ATS=8: rows are 32B and 16B-aligned -> operand loads via ulonglong2
// (LDS.128, broadcast so conflict-free).  7 warps/block, 2 blocks/SM.
#define FG_WARPS 7
#define FG_THREADS (FG_WARPS * 32)
#define ATS 8
#define OFF_W2 8192
#define OFF_B1 16384
#define OFF_AT 16512
#define OFF_HT (OFF_AT + FG_WARPS * (F * ATS))
#define FG_FLOATS (OFF_HT + FG_WARPS * (HID * ATS))
#define FG_BYTES (FG_FLOATS * 4)

__global__ void __launch_bounds__(FG_THREADS, 2)
k_fused(const float* __restrict__ W1, const float* __restrict__ b1,
        const float* __restrict__ W2, int n) {
    extern __shared__ float smem[];
    float* W1s = smem;
    float* W2s = smem + OFF_W2;
    float* b1s = smem + OFF_B1;
    int tid = threadIdx.x;
    int warp = tid >> 5;
    int lane = tid & 31;

    for (int j = tid; j < (F * HID) / 4; j += FG_THREADS)
        ((float4*)W1s)[j] = ((const float4*)W1)[j];
    for (int j = tid; j < (HID * F) / 4; j += FG_THREADS)
        ((float4*)W2s)[j] = ((const float4*)W2)[j];
    for (int j = tid; j < HID; j += FG_THREADS) b1s[j] = b1[j];
    __syncthreads();

    int nbase = (blockIdx.x * FG_WARPS + warp) * 8;
    if (nbase >= n) return;
    float* aTw = smem + OFF_AT + warp * (F * ATS);
    float* hTw = smem + OFF_HT + warp * (HID * ATS);

#pragma unroll
    for (int ni = 0; ni < 8; ni++) {
        int node = nbase + ni;
        float a0 = 0.f, a1 = 0.f;
        if (node < n) {
            a0 = g_agg[(size_t)node * F + lane];
            a1 = g_agg[(size_t)node * F + 32 + lane];
        }
        aTw[lane * ATS + ni] = a0;
        aTw[(lane + 32) * ATS + ni] = a1;
    }
    __syncwarp();

    // ---- layer 1: acc1[p][j] = packed (node 2p, 2p+1) at col lane+32j
    ull acc1[4][4];
#pragma unroll
    for (int p = 0; p < 4; p++)
#pragma unroll
        for (int j = 0; j < 4; j++) acc1[p][j] = 0ull;

#pragma unroll 4
    for (int k = 0; k < F; k++) {
        const ulonglong2* ar2 = (const ulonglong2*)(aTw + k * ATS);
        ulonglong2 A = ar2[0];
        ulonglong2 B = ar2[1];
        ull a0 = A.x, a1 = A.y, a2 = B.x, a3 = B.y;
        const float* wr = W1s + k * HID + lane;
        ull w0 = pack2(wr[0], wr[0]);
        ull w1 = pack2(wr[32], wr[32]);
        ull w2 = pack2(wr[64], wr[64]);
        ull w3 = pack2(wr[96], wr[96]);
        acc1[0][0] = ffma2(a0, w0, acc1[0][0]);
        acc1[0][1] = ffma2(a0, w1, acc1[0][1]);
        acc1[0][2] = ffma2(a0, w2, acc1[0][2]);
        acc1[0][3] = ffma2(a0, w3, acc1[0][3]);
        acc1[1][0] = ffma2(a1, w0, acc1[1][0]);
        acc1[1][1] = ffma2(a1, w1, acc1[1][1]);
        acc1[1][2] = ffma2(a1, w2, acc1[1][2]);
        acc1[1][3] = ffma2(a1, w3, acc1[1][3]);
        acc1[2][0] = ffma2(a2, w0, acc1[2][0]);
        acc1[2][1] = ffma2(a2, w1, acc1[2][1]);
        acc1[2][2] = ffma2(a2, w2, acc1[2][2]);
        acc1[2][3] = ffma2(a2, w3, acc1[2][3]);
        acc1[3][0] = ffma2(a3, w0, acc1[3][0]);
        acc1[3][1] = ffma2(a3, w1, acc1[3][1]);
        acc1[3][2] = ffma2(a3, w2, acc1[3][2]);
        acc1[3][3] = ffma2(a3, w3, acc1[3][3]);
    }

    // bias + relu -> hT
#pragma unroll
    for (int j = 0; j < 4; j++) {
        float bb = b1s[lane + 32 * j];
        float* hrow = hTw + (lane + 32 * j) * ATS;
#pragma unroll
        for (int p = 0; p < 4; p++) {
            float lo, hi;
            unpack2(acc1[p][j], lo, hi);
            lo = fmaxf(lo + bb, 0.f);
            hi = fmaxf(hi + bb, 0.f);
            ((ull*)hrow)[p] = pack2(lo, hi);
        }
    }
    __syncwarp();

    // ---- layer 2
    ull t0[4], t1[4];
#pragma unroll
    for (int p = 0; p < 4; p++) { t0[p] = 0ull; t1[p] = 0ull; }

#pragma unroll 2
    for (int k = 0; k < HID; k++) {
        const ulonglong2* hr2 = (const ulonglong2*)(hTw + k * ATS);
        ulonglong2 A = hr2[0];
        ulonglong2 B = hr2[1];
        ull h0 = A.x, h1 = A.y, h2 = B.x, h3 = B.y;
        float u0 = W2s[k * F + lane];
        float u1 = W2s[k * F + lane + 32];
        ull up0 = pack2(u0, u0);
        ull up1 = pack2(u1, u1);
        t0[0] = ffma2(h0, up0, t0[0]);
        t0[1] = ffma2(h1, up0, t0[1]);
        t0[2] = ffma2(h2, up0, t0[2]);
        t0[3] = ffma2(h3, up0, t0[3]);
        t1[0] = ffma2(h0, up1, t1[0]);
        t1[1] = ffma2(h1, up1, t1[1]);
        t1[2] = ffma2(h2, up1, t1[2]);
        t1[3] = ffma2(h3, up1, t1[3]);
    }

    // tsh = fp16(t * dinv) -> g_tsh
#pragma unroll
    for (int p = 0; p < 4; p++) {
        int n0 = nbase + 2 * p;
        int n1 = n0 + 1;
        float lo0, hi0, lo1, hi1;
        unpack2(t0[p], lo0, hi0);
        unpack2(t1[p], lo1, hi1);
        if (n0 < n) {
            float dv = g_dinv[n0];
            g_tsh[(size_t)n0 * F + lane] = __float2half_rn(lo0 * dv);
            g_tsh[(size_t)n0 * F + 32 + lane] = __float2half_rn(lo1 * dv);
        }
        if (n1 < n) {
            float dv = g_dinv[n1];
            g_tsh[(size_t)n1 * F + lane] = __float2half_rn(hi0 * dv);
            g_tsh[(size_t)n1 * F + 32 + lane] = __float2half_rn(hi1 * dv);
        }
    }
}

// ---------------------------------------------------------------- launch
extern "C" void kernel_launch(void* const* d_in, const int* in_sizes, int n_in,
                              void* d_out, int out_size) {
    const float* x  = (const float*)d_in[0];
    const int* ei   = (const int*)d_in[1];   // int32 edge_index [2, E]
    const float* W1 = (const float*)d_in[2];
    const float* b1 = (const float*)d_in[3];
    const float* W2 = (const float*)d_in[4];
    const float* b2 = (const float*)d_in[5];
    float* out      = (float*)d_out;

    int n = in_sizes[0] / F;   // 100000
    int E = in_sizes[1] / 2;   // 1600000
    const int* src = ei;
    const int* dst = ei + E;

    cudaFuncSetAttribute(k_fused, cudaFuncAttributeMaxDynamicSharedMemorySize,
                         FG_BYTES);

    int nbN = (n + 255) / 256;
    int nbE = (E + 255) / 256;

    // CSR build (+ fused dinv + fp16 prep)
    k_zero<<<nbN, 256>>>(n);
    k_hist<<<nbE, 256>>>(dst, E);
    k_alloc<<<nbN, 256>>>(x, n);
    k_permute<<<(E / 2 + 255) / 256, 256>>>(src, dst, E);

    // layer 1 aggregation
    int gth_blocks = (n * 32 + 255) / 256;
    k_gather<0><<<gth_blocks, 256>>>(nullptr, nullptr, n);

    // fused double GEMM
    int fg_blocks = ((n + 7) / 8 + FG_WARPS - 1) / FG_WARPS;
    k_fused<<<fg_blocks, FG_THREADS, FG_BYTES>>>(W1, b1, W2, n);

    // layer 2 aggregation + epilogue
    k_gather<1><<<gth_blocks, 256>>>(b2, out, n);
}

// round 12
// speedup vs baseline: 1.8414x; 1.4368x over previous
#include <cuda_runtime.h>
#include <cuda_fp16.h>

// GCN 2-layer, CSR-gather aggregation, tensor-core (HMMA m16n8k16) fused GEMM,
// fp16 gather payloads and fp16 GEMM inputs (fp32 accumulate).
//   count = indegree;  dinv = rsqrt(1+count);  CSR rows via warp-aggregated
//   atomicAdd allocation;  xh = fp16(x*dinv) fused into k_alloc.
//   ah   = fp16((sum_{s in N(d)+self} xh[s]) * dinv[d])    (gather1 -> g_ah)
//   h1   = relu(ah @ W1 + b1)  }  fused mma.sync kernel; h1 stays in C-frags,
//   tsh  = fp16((h1 @ W2)*dinv)}  C-pair -> A-frag identity feeds layer 2
//   out  = (sum tsh[s incl self]) * dinv[d] + b2           (gather2 -> out)
// edge_index int32.  Device symbols touched ONLY from device code (GB300 ATS
// makes host-side symbol addresses silently read host memory).

#define NMAX 100000
#define EMAX 1600000
#define F 64
#define HID 128

__device__ float g_dinv[NMAX];
__device__ __half g_xh[NMAX * F];    // fp16 pre-scaled x
__device__ __half g_ah[NMAX * F];    // fp16 layer-1 aggregated activations
__device__ __half g_tsh[NMAX * F];   // fp16 pre-scaled layer-2 activations

__device__ int g_count[NMAX];
__device__ int g_row_start[NMAX];
__device__ int g_cursor[NMAX];
__device__ int g_csr[EMAX];
__device__ int g_total;

// ---------------------------------------------------------------- mma helper
__device__ __forceinline__ unsigned h2u(__half2 h) { return *(unsigned*)&h; }

__device__ __forceinline__ void mma16816(float c[4],
                                         unsigned a0, unsigned a1,
                                         unsigned a2, unsigned a3,
                                         unsigned b0, unsigned b1) {
    asm volatile(
        "mma.sync.aligned.m16n8k16.row.col.f32.f16.f16.f32 "
        "{%0,%1,%2,%3}, {%4,%5,%6,%7}, {%8,%9}, {%0,%1,%2,%3};"
        : "+f"(c[0]), "+f"(c[1]), "+f"(c[2]), "+f"(c[3])
        : "r"(a0), "r"(a1), "r"(a2), "r"(a3), "r"(b0), "r"(b1));
}

// ---------------------------------------------------------------- CSR build
__global__ void k_zero(int n) {
    int i = blockIdx.x * blockDim.x + threadIdx.x;
    if (i == 0) g_total = 0;
    if (i < n) g_count[i] = 0;
}

__global__ void k_hist(const int* __restrict__ dst, int E) {
    int i = blockIdx.x * blockDim.x + threadIdx.x;
    if (i < E) atomicAdd(&g_count[__ldg(&dst[i])], 1);
}

// Row allocation (warp scan + one atomicAdd per warp) + dinv + fp16 prep.
__global__ void k_alloc(const float* __restrict__ x, int n) {
    int i = blockIdx.x * blockDim.x + threadIdx.x;
    int lane = threadIdx.x & 31;
    int cnt = (i < n) ? g_count[i] : 0;
    int sum = cnt;
#pragma unroll
    for (int off = 1; off < 32; off <<= 1) {
        int v = __shfl_up_sync(0xffffffffu, sum, off);
        if (lane >= off) sum += v;
    }
    int total = __shfl_sync(0xffffffffu, sum, 31);
    int base = 0;
    if (lane == 0) base = atomicAdd(&g_total, total);
    base = __shfl_sync(0xffffffffu, base, 0);
    int start = base + sum - cnt;
    if (i < n) {
        g_row_start[i] = start;
        g_cursor[i] = start;
        float dv = rsqrtf(1.0f + (float)cnt);
        g_dinv[i] = dv;
        const float4* xr = (const float4*)(x + (size_t)i * F);
        uint2* o = (uint2*)(g_xh + (size_t)i * F);
#pragma unroll
        for (int q = 0; q < 16; q++) {
            float4 v = xr[q];
            __half2 h0 = __floats2half2_rn(v.x * dv, v.y * dv);
            __half2 h1 = __floats2half2_rn(v.z * dv, v.w * dv);
            uint2 u;
            u.x = h2u(h0);
            u.y = h2u(h1);
            o[q] = u;
        }
    }
}

__global__ void k_permute(const int* __restrict__ src,
                          const int* __restrict__ dst, int E) {
    int i = (blockIdx.x * blockDim.x + threadIdx.x) * 2;
    if (i + 1 < E) {
        int d0 = __ldg(&dst[i]);
        int d1 = __ldg(&dst[i + 1]);
        int s0 = __ldg(&src[i]);
        int s1 = __ldg(&src[i + 1]);
        int p0 = atomicAdd(&g_cursor[d0], 1);
        int p1 = atomicAdd(&g_cursor[d1], 1);
        g_csr[p0] = s0;
        g_csr[p1] = s1;
    } else if (i < E) {
        int p = atomicAdd(&g_cursor[__ldg(&dst[i])], 1);
        g_csr[p] = __ldg(&src[i]);
    }
}

// ---------------------------------------------------------------- gathers
// One warp per dst node.  4 groups of 8 lanes; each lane loads uint4
// (16B = 8 fp16 feats); 2-deep unroll.  Groups merged via shfl_down.
// MODE 0: source g_xh -> fp16(acc*dinv[d]) -> g_ah
// MODE 1: source g_tsh -> acc*dinv[d] + b2 -> out (fp32)
__device__ __forceinline__ void acc_row(float* acc, uint4 r) {
    float2 p0 = __half22float2(*(__half2*)&r.x);
    float2 p1 = __half22float2(*(__half2*)&r.y);
    float2 p2 = __half22float2(*(__half2*)&r.z);
    float2 p3 = __half22float2(*(__half2*)&r.w);
    acc[0] += p0.x; acc[1] += p0.y;
    acc[2] += p1.x; acc[3] += p1.y;
    acc[4] += p2.x; acc[5] += p2.y;
    acc[6] += p3.x; acc[7] += p3.y;
}

template <int MODE>
__global__ void __launch_bounds__(256)
k_gather(const float* __restrict__ b2, float* __restrict__ outparam, int n) {
    int gwarp = (blockIdx.x * blockDim.x + threadIdx.x) >> 5;
    if (gwarp >= n) return;
    int lane = threadIdx.x & 31;
    int d = gwarp;
    int g = lane >> 3;     // edge group 0-3
    int t = lane & 7;      // 16B chunk within row

    const uint4* bh = (MODE == 0) ? (const uint4*)g_xh : (const uint4*)g_tsh;
    float acc[8];
#pragma unroll
    for (int q = 0; q < 8; q++) acc[q] = 0.f;

    int start = g_row_start[d];
    int end = start + g_count[d];
    int e = start + g;
    for (; e + 4 < end; e += 8) {
        int s0 = __ldg(&g_csr[e]);
        int s1 = __ldg(&g_csr[e + 4]);
        uint4 r0 = bh[(size_t)s0 * 8 + t];
        uint4 r1 = bh[(size_t)s1 * 8 + t];
        acc_row(acc, r0);
        acc_row(acc, r1);
    }
    if (e < end) {
        int s = __ldg(&g_csr[e]);
        uint4 r = bh[(size_t)s * 8 + t];
        acc_row(acc, r);
    }

#pragma unroll
    for (int q = 0; q < 8; q++) {
        acc[q] += __shfl_down_sync(0xffffffffu, acc[q], 16);
        acc[q] += __shfl_down_sync(0xffffffffu, acc[q], 8);
    }

    if (g == 0) {
        uint4 sv = bh[(size_t)d * 8 + t];     // self loop
        acc_row(acc, sv);
        float dvd = g_dinv[d];
#pragma unroll
        for (int q = 0; q < 8; q++) acc[q] *= dvd;
        if (MODE == 0) {
            uint4 u;
            u.x = h2u(__floats2half2_rn(acc[0], acc[1]));
            u.y = h2u(__floats2half2_rn(acc[2], acc[3]));
            u.z = h2u(__floats2half2_rn(acc[4], acc[5]));
            u.w = h2u(__floats2half2_rn(acc[6], acc[7]));
            ((uint4*)g_ah)[(size_t)d * 8 + t] = u;
        } else {
            float4 o0 = make_float4(acc[0], acc[1], acc[2], acc[3]);
            float4 o1 = make_float4(acc[4], acc[5], acc[6], acc[7]);
            float4 bb0 = ((const float4*)b2)[t * 2];
            float4 bb1 = ((const float4*)b2)[t * 2 + 1];
            o0.x += bb0.x; o0.y += bb0.y; o0.z += bb0.z; o0.w += bb0.w;
            o1.x += bb1.x; o1.y += bb1.y; o1.z += bb1.z; o1.w += bb1.w;
            ((float4*)outparam)[(size_t)d * 16 + t * 2] = o0;
            ((float4*)outparam)[(size_t)d * 16 + t * 2 + 1] = o1;
        }
    }
}

// ---------------------------------------------------------------- fused GEMMs
// Tensor-core version.  Block = 128 nodes, 8 warps; warp w owns m16 strip
// rows [16w, 16w+16).  Layer1: A(m16k16 from g_ah tile) x W1T -> 16 n8 C
// fragments (fp32).  Bias+relu in-register; C-tile pair == A-fragment for
// layer2 (m16n8 C pair layout == m16k16 A layout).  Layer2 x W2T -> 8 n8 C,
// scaled by dinv and stored fp16 to g_tsh.
// smem (halves): W1T[128][72] | W2T[64][136] | AT[128][72] | b1 (fp32, tail)
#define SW1 0
#define SW2 (128 * 72)                 // 9216
#define SAT (SW2 + 64 * 136)           // 17920
#define SB1 (SAT + 128 * 72)           // 27136 halves = 54272 bytes
#define FB_BYTES (SB1 * 2 + 128 * 4)   // 54784

__global__ void __launch_bounds__(256)
k_fused(const float* __restrict__ W1, const float* __restrict__ b1,
        const float* __restrict__ W2, int n) {
    extern __shared__ __half smh[];
    float* b1s = (float*)(smh + SB1);
    int tid = threadIdx.x;
    int base = blockIdx.x * 128;

    // stage weights (fp32 -> fp16, transposed to n-major) and bias
    for (int i = tid; i < F * HID; i += 256) {        // W1 [k=64][n=128]
        int k = i >> 7, nn = i & 127;
        smh[SW1 + nn * 72 + k] = __float2half_rn(W1[i]);
    }
    for (int i = tid; i < HID * F; i += 256) {        // W2 [k=128][n=64]
        int k = i >> 6, nn = i & 63;
        smh[SW2 + nn * 136 + k] = __float2half_rn(W2[i]);
    }
    if (tid < HID) b1s[tid] = b1[tid];
    // stage activation tile (fp16, row pad 8 halves)
    for (int i = tid; i < 128 * 8; i += 256) {
        int r = i >> 3, q = i & 7;
        uint4 v = make_uint4(0u, 0u, 0u, 0u);
        if (base + r < n) v = ((const uint4*)g_ah)[(size_t)(base + r) * 8 + q];
        *(uint4*)&smh[SAT + r * 72 + q * 8] = v;
    }
    __syncthreads();

    int warp = tid >> 5;
    int lane = tid & 31;
    int tr = lane >> 2;        // group id (0-7)
    int tc = lane & 3;         // thread in group
    int rbase = warp * 16;

    // ---- layer 1: c1[nt] covers cols [8nt, 8nt+8)
    float c1[16][4];
#pragma unroll
    for (int nt = 0; nt < 16; nt++)
#pragma unroll
        for (int q = 0; q < 4; q++) c1[nt][q] = 0.f;

#pragma unroll
    for (int kt = 0; kt < 4; kt++) {
        int klo = kt * 16 + 2 * tc;
        unsigned a0 = *(const unsigned*)&smh[SAT + (rbase + tr) * 72 + klo];
        unsigned a1 = *(const unsigned*)&smh[SAT + (rbase + tr + 8) * 72 + klo];
        unsigned a2 = *(const unsigned*)&smh[SAT + (rbase + tr) * 72 + klo + 8];
        unsigned a3 = *(const unsigned*)&smh[SAT + (rbase + tr + 8) * 72 + klo + 8];
#pragma unroll
        for (int nt = 0; nt < 16; nt++) {
            unsigned bb0 = *(const unsigned*)&smh[SW1 + (nt * 8 + tr) * 72 + klo];
            unsigned bb1 = *(const unsigned*)&smh[SW1 + (nt * 8 + tr) * 72 + klo + 8];
            mma16816(c1[nt], a0, a1, a2, a3, bb0, bb1);
        }
    }

    // bias + relu (cols of c0/c2 = 8nt+2tc, c1/c3 = +1)
#pragma unroll
    for (int nt = 0; nt < 16; nt++) {
        float bb0 = b1s[nt * 8 + 2 * tc];
        float bb1 = b1s[nt * 8 + 2 * tc + 1];
        c1[nt][0] = fmaxf(c1[nt][0] + bb0, 0.f);
        c1[nt][1] = fmaxf(c1[nt][1] + bb1, 0.f);
        c1[nt][2] = fmaxf(c1[nt][2] + bb0, 0.f);
        c1[nt][3] = fmaxf(c1[nt][3] + bb1, 0.f);
    }

    // ---- layer 2: C-pair (2j, 2j+1) is the A-fragment for k-tile j
    float c2r[8][4];
#pragma unroll
    for (int nt = 0; nt < 8; nt++)
#pragma unroll
        for (int q = 0; q < 4; q++) c2r[nt][q] = 0.f;

#pragma unroll
    for (int j = 0; j < 8; j++) {
        unsigned a0 = h2u(__floats2half2_rn(c1[2 * j][0], c1[2 * j][1]));
        unsigned a1 = h2u(__floats2half2_rn(c1[2 * j][2], c1[2 * j][3]));
        unsigned a2 = h2u(__floats2half2_rn(c1[2 * j + 1][0], c1[2 * j + 1][1]));
        unsigned a3 = h2u(__floats2half2_rn(c1[2 * j + 1][2], c1[2 * j + 1][3]));
        int klo = j * 16 + 2 * tc;
#pragma unroll
        for (int nt = 0; nt < 8; nt++) {
            unsigned bb0 = *(const unsigned*)&smh[SW2 + (nt * 8 + tr) * 136 + klo];
            unsigned bb1 = *(const unsigned*)&smh[SW2 + (nt * 8 + tr) * 136 + klo + 8];
            mma16816(c2r[nt], a0, a1, a2, a3, bb0, bb1);
        }
    }

    // epilogue: tsh = fp16(t * dinv)
    int nz0 = base + rbase + tr;
    int nz1 = nz0 + 8;
    float dv0 = (nz0 < n) ? g_dinv[nz0] : 0.f;
    float dv1 = (nz1 < n) ? g_dinv[nz1] : 0.f;
#pragma unroll
    for (int nt = 0; nt < 8; nt++) {
        int col = nt * 8 + 2 * tc;
        if (nz0 < n)
            *(__half2*)&g_tsh[(size_t)nz0 * F + col] =
                __floats2half2_rn(c2r[nt][0] * dv0, c2r[nt][1] * dv0);
        if (nz1 < n)
            *(__half2*)&g_tsh[(size_t)nz1 * F + col] =
                __floats2half2_rn(c2r[nt][2] * dv1, c2r[nt][3] * dv1);
    }
}

// ---------------------------------------------------------------- launch
extern "C" void kernel_launch(void* const* d_in, const int* in_sizes, int n_in,
                              void* d_out, int out_size) {
    const float* x  = (const float*)d_in[0];
    const int* ei   = (const int*)d_in[1];   // int32 edge_index [2, E]
    const float* W1 = (const float*)d_in[2];
    const float* b1 = (const float*)d_in[3];
    const float* W2 = (const float*)d_in[4];
    const float* b2 = (const float*)d_in[5];
    float* out      = (float*)d_out;

    int n = in_sizes[0] / F;   // 100000
    int E = in_sizes[1] / 2;   // 1600000
    const int* src = ei;
    const int* dst = ei + E;

    cudaFuncSetAttribute(k_fused, cudaFuncAttributeMaxDynamicSharedMemorySize,
                         FB_BYTES);

    int nbN = (n + 255) / 256;
    int nbE = (E + 255) / 256;

    // CSR build (+ fused dinv + fp16 prep)
    k_zero<<<nbN, 256>>>(n);
    k_hist<<<nbE, 256>>>(dst, E);
    k_alloc<<<nbN, 256>>>(x, n);
    k_permute<<<(E / 2 + 255) / 256, 256>>>(src, dst, E);

    // layer 1 aggregation -> fp16 activations
    int gth_blocks = (n * 32 + 255) / 256;
    k_gather<0><<<gth_blocks, 256>>>(nullptr, nullptr, n);

    // fused tensor-core double GEMM
    k_fused<<<(n + 127) / 128, 256, FB_BYTES>>>(W1, b1, W2, n);

    // layer 2 aggregation + epilogue
    k_gather<1><<<gth_blocks, 256>>>(b2, out, n);
}

// round 13
// speedup vs baseline: 2.0171x; 1.0954x over previous
#include <cuda_runtime.h>
#include <cuda_fp16.h>

// GCN 2-layer, CSR-gather aggregation, tensor-core (HMMA m16n8k16) fused GEMM,
// fp16 gather payloads, PDL-overlapped launch chain:
//   zero -> hist -> alloc(scan+dinv) -> permute(trigger@entry)
//        -> prep[PDL] (fp16(x*dinv), overlaps permute)
//        -> gather1(trigger@entry) -> fused[PDL] (stage weights, wait, mma;
//           trigger@entry) -> gather2[PDL] (meta loads, wait, loop)
// edge_index int32.  Device symbols touched ONLY from device code (GB300 ATS
// makes host-side symbol addresses silently read host memory).

#define NMAX 100000
#define EMAX 1600000
#define F 64
#define HID 128

__device__ float g_dinv[NMAX];
__device__ __half g_xh[NMAX * F];    // fp16 pre-scaled x
__device__ __half g_ah[NMAX * F];    // fp16 layer-1 aggregated activations
__device__ __half g_tsh[NMAX * F];   // fp16 pre-scaled layer-2 activations

__device__ int g_count[NMAX];
__device__ int g_row_start[NMAX];
__device__ int g_cursor[NMAX];
__device__ int g_csr[EMAX];
__device__ int g_total;

// ---------------------------------------------------------------- helpers
__device__ __forceinline__ unsigned h2u(__half2 h) { return *(unsigned*)&h; }

__device__ __forceinline__ void pdl_trigger() {
    asm volatile("griddepcontrol.launch_dependents;" ::: "memory");
}
__device__ __forceinline__ void pdl_wait() {
    asm volatile("griddepcontrol.wait;" ::: "memory");
}

__device__ __forceinline__ void mma16816(float c[4],
                                         unsigned a0, unsigned a1,
                                         unsigned a2, unsigned a3,
                                         unsigned b0, unsigned b1) {
    asm volatile(
        "mma.sync.aligned.m16n8k16.row.col.f32.f16.f16.f32 "
        "{%0,%1,%2,%3}, {%4,%5,%6,%7}, {%8,%9}, {%0,%1,%2,%3};"
        : "+f"(c[0]), "+f"(c[1]), "+f"(c[2]), "+f"(c[3])
        : "r"(a0), "r"(a1), "r"(a2), "r"(a3), "r"(b0), "r"(b1));
}

// ---------------------------------------------------------------- CSR build
__global__ void k_zero(int n) {
    int i = blockIdx.x * blockDim.x + threadIdx.x;
    if (i == 0) g_total = 0;
    if (i < n) g_count[i] = 0;
}

__global__ void k_hist(const int* __restrict__ dst, int E) {
    int i = blockIdx.x * blockDim.x + threadIdx.x;
    if (i < E) atomicAdd(&g_count[__ldg(&dst[i])], 1);
}

// Row allocation (warp scan + one atomicAdd per warp) + dinv.
__global__ void k_alloc(int n) {
    int i = blockIdx.x * blockDim.x + threadIdx.x;
    int lane = threadIdx.x & 31;
    int cnt = (i < n) ? g_count[i] : 0;
    int sum = cnt;
#pragma unroll
    for (int off = 1; off < 32; off <<= 1) {
        int v = __shfl_up_sync(0xffffffffu, sum, off);
        if (lane >= off) sum += v;
    }
    int total = __shfl_sync(0xffffffffu, sum, 31);
    int base = 0;
    if (lane == 0) base = atomicAdd(&g_total, total);
    base = __shfl_sync(0xffffffffu, base, 0);
    int start = base + sum - cnt;
    if (i < n) {
        g_row_start[i] = start;
        g_cursor[i] = start;
        g_dinv[i] = rsqrtf(1.0f + (float)cnt);
    }
}

// Triggers at entry so k_prep (PDL) overlaps with it.
__global__ void k_permute(const int* __restrict__ src,
                          const int* __restrict__ dst, int E) {
    pdl_trigger();
    int i = (blockIdx.x * blockDim.x + threadIdx.x) * 2;
    if (i + 1 < E) {
        int d0 = __ldg(&dst[i]);
        int d1 = __ldg(&dst[i + 1]);
        int s0 = __ldg(&src[i]);
        int s1 = __ldg(&src[i + 1]);
        int p0 = atomicAdd(&g_cursor[d0], 1);
        int p1 = atomicAdd(&g_cursor[d1], 1);
        g_csr[p0] = s0;
        g_csr[p1] = s1;
    } else if (i < E) {
        int p = atomicAdd(&g_cursor[__ldg(&dst[i])], 1);
        g_csr[p] = __ldg(&src[i]);
    }
}

// xh = fp16(x * dinv[row]).  PDL dependent of k_permute; reads only
// g_dinv (from k_alloc, complete before k_permute could start) and x.
__global__ void k_prep(const float* __restrict__ x, int n) {
    int i = blockIdx.x * blockDim.x + threadIdx.x;
    if (i >= n * 16) return;
    int node = i >> 4;
    float dv = g_dinv[node];
    float4 v = ((const float4*)x)[i];
    uint2 u;
    u.x = h2u(__floats2half2_rn(v.x * dv, v.y * dv));
    u.y = h2u(__floats2half2_rn(v.z * dv, v.w * dv));
    ((uint2*)g_xh)[i] = u;
}

// ---------------------------------------------------------------- gathers
// One warp per dst node.  4 groups of 8 lanes; each lane loads uint4
// (16B = 8 fp16 feats); 2-deep unroll.  Groups merged via shfl_down.
// MODE 0: source g_xh -> fp16(acc*dinv[d]) -> g_ah   (triggers at entry)
// MODE 1: source g_tsh -> acc*dinv[d] + b2 -> out    (PDL: meta loads, wait)
__device__ __forceinline__ void acc_row(float* acc, uint4 r) {
    float2 p0 = __half22float2(*(__half2*)&r.x);
    float2 p1 = __half22float2(*(__half2*)&r.y);
    float2 p2 = __half22float2(*(__half2*)&r.z);
    float2 p3 = __half22float2(*(__half2*)&r.w);
    acc[0] += p0.x; acc[1] += p0.y;
    acc[2] += p1.x; acc[3] += p1.y;
    acc[4] += p2.x; acc[5] += p2.y;
    acc[6] += p3.x; acc[7] += p3.y;
}

template <int MODE>
__global__ void __launch_bounds__(256)
k_gather(const float* __restrict__ b2, float* __restrict__ outparam, int n) {
    if (MODE == 0) pdl_trigger();   // let k_fused start staging weights
    int gwarp = (blockIdx.x * blockDim.x + threadIdx.x) >> 5;
    if (gwarp >= n) {
        if (MODE == 1) pdl_wait();
        return;
    }
    int lane = threadIdx.x & 31;
    int d = gwarp;
    int g = lane >> 3;     // edge group 0-3
    int t = lane & 7;      // 16B chunk within row

    // meta loads: row_start/count/dinv come from k_alloc (long complete),
    // safe to issue before the PDL wait in MODE 1.
    int start = g_row_start[d];
    int cnt = g_count[d];
    float dvd = g_dinv[d];
    if (MODE == 1) pdl_wait();      // g_tsh becomes valid

    const uint4* bh = (MODE == 0) ? (const uint4*)g_xh : (const uint4*)g_tsh;
    float acc[8];
#pragma unroll
    for (int q = 0; q < 8; q++) acc[q] = 0.f;

    int end = start + cnt;
    int e = start + g;
    for (; e + 4 < end; e += 8) {
        int s0 = __ldg(&g_csr[e]);
        int s1 = __ldg(&g_csr[e + 4]);
        uint4 r0 = bh[(size_t)s0 * 8 + t];
        uint4 r1 = bh[(size_t)s1 * 8 + t];
        acc_row(acc, r0);
        acc_row(acc, r1);
    }
    if (e < end) {
        int s = __ldg(&g_csr[e]);
        uint4 r = bh[(size_t)s * 8 + t];
        acc_row(acc, r);
    }

#pragma unroll
    for (int q = 0; q < 8; q++) {
        acc[q] += __shfl_down_sync(0xffffffffu, acc[q], 16);
        acc[q] += __shfl_down_sync(0xffffffffu, acc[q], 8);
    }

    if (g == 0) {
        uint4 sv = bh[(size_t)d * 8 + t];     // self loop
        acc_row(acc, sv);
#pragma unroll
        for (int q = 0; q < 8; q++) acc[q] *= dvd;
        if (MODE == 0) {
            uint4 u;
            u.x = h2u(__floats2half2_rn(acc[0], acc[1]));
            u.y = h2u(__floats2half2_rn(acc[2], acc[3]));
            u.z = h2u(__floats2half2_rn(acc[4], acc[5]));
            u.w = h2u(__floats2half2_rn(acc[6], acc[7]));
            ((uint4*)g_ah)[(size_t)d * 8 + t] = u;
        } else {
            float4 o0 = make_float4(acc[0], acc[1], acc[2], acc[3]);
            float4 o1 = make_float4(acc[4], acc[5], acc[6], acc[7]);
            float4 bb0 = ((const float4*)b2)[t * 2];
            float4 bb1 = ((const float4*)b2)[t * 2 + 1];
            o0.x += bb0.x; o0.y += bb0.y; o0.z += bb0.z; o0.w += bb0.w;
            o1.x += bb1.x; o1.y += bb1.y; o1.z += bb1.z; o1.w += bb1.w;
            ((float4*)outparam)[(size_t)d * 16 + t * 2] = o0;
            ((float4*)outparam)[(size_t)d * 16 + t * 2 + 1] = o1;
        }
    }
}

// ---------------------------------------------------------------- fused GEMMs
// Tensor-core version.  Block = 128 nodes, 8 warps; warp w owns m16 strip.
// PDL dependent of gather1: stages weights (inputs only) before the wait,
// then activation tile + mma.  Triggers at entry so gather2 starts early.
// smem (halves): W1T[128][72] | W2T[64][136] | AT[128][72] | b1 (fp32, tail)
#define SW1 0
#define SW2 (128 * 72)                 // 9216
#define SAT (SW2 + 64 * 136)           // 17920
#define SB1 (SAT + 128 * 72)           // 27136 halves = 54272 bytes
#define FB_BYTES (SB1 * 2 + 128 * 4)   // 54784

__global__ void __launch_bounds__(256)
k_fused(const float* __restrict__ W1, const float* __restrict__ b1,
        const float* __restrict__ W2, int n) {
    pdl_trigger();                      // let gather2 start its meta loads
    extern __shared__ __half smh[];
    float* b1s = (float*)(smh + SB1);
    int tid = threadIdx.x;
    int base = blockIdx.x * 128;

    // stage weights (fp32 -> fp16, transposed to n-major) and bias — inputs
    for (int i = tid; i < F * HID; i += 256) {        // W1 [k=64][n=128]
        int k = i >> 7, nn = i & 127;
        smh[SW1 + nn * 72 + k] = __float2half_rn(W1[i]);
    }
    for (int i = tid; i < HID * F; i += 256) {        // W2 [k=128][n=64]
        int k = i >> 6, nn = i & 63;
        smh[SW2 + nn * 136 + k] = __float2half_rn(W2[i]);
    }
    if (tid < HID) b1s[tid] = b1[tid];

    pdl_wait();                         // gather1 complete -> g_ah valid

    // stage activation tile (fp16, row pad 8 halves)
    for (int i = tid; i < 128 * 8; i += 256) {
        int r = i >> 3, q = i & 7;
        uint4 v = make_uint4(0u, 0u, 0u, 0u);
        if (base + r < n) v = ((const uint4*)g_ah)[(size_t)(base + r) * 8 + q];
        *(uint4*)&smh[SAT + r * 72 + q * 8] = v;
    }
    __syncthreads();

    int warp = tid >> 5;
    int lane = tid & 31;
    int tr = lane >> 2;        // group id (0-7)
    int tc = lane & 3;         // thread in group
    int rbase = warp * 16;

    // ---- layer 1: c1[nt] covers cols [8nt, 8nt+8)
    float c1[16][4];
#pragma unroll
    for (int nt = 0; nt < 16; nt++)
#pragma unroll
        for (int q = 0; q < 4; q++) c1[nt][q] = 0.f;

#pragma unroll
    for (int kt = 0; kt < 4; kt++) {
        int klo = kt * 16 + 2 * tc;
        unsigned a0 = *(const unsigned*)&smh[SAT + (rbase + tr) * 72 + klo];
        unsigned a1 = *(const unsigned*)&smh[SAT + (rbase + tr + 8) * 72 + klo];
        unsigned a2 = *(const unsigned*)&smh[SAT + (rbase + tr) * 72 + klo + 8];
        unsigned a3 = *(const unsigned*)&smh[SAT + (rbase + tr + 8) * 72 + klo + 8];
#pragma unroll
        for (int nt = 0; nt < 16; nt++) {
            unsigned bb0 = *(const unsigned*)&smh[SW1 + (nt * 8 + tr) * 72 + klo];
            unsigned bb1 = *(const unsigned*)&smh[SW1 + (nt * 8 + tr) * 72 + klo + 8];
            mma16816(c1[nt], a0, a1, a2, a3, bb0, bb1);
        }
    }

    // bias + relu (cols of c0/c2 = 8nt+2tc, c1/c3 = +1)
#pragma unroll
    for (int nt = 0; nt < 16; nt++) {
        float bb0 = b1s[nt * 8 + 2 * tc];
        float bb1 = b1s[nt * 8 + 2 * tc + 1];
        c1[nt][0] = fmaxf(c1[nt][0] + bb0, 0.f);
        c1[nt][1] = fmaxf(c1[nt][1] + bb1, 0.f);
        c1[nt][2] = fmaxf(c1[nt][2] + bb0, 0.f);
        c1[nt][3] = fmaxf(c1[nt][3] + bb1, 0.f);
    }

    // ---- layer 2: C-pair (2j, 2j+1) is the A-fragment for k-tile j
    float c2r[8][4];
#pragma unroll
    for (int nt = 0; nt < 8; nt++)
#pragma unroll
        for (int q = 0; q < 4; q++) c2r[nt][q] = 0.f;

#pragma unroll
    for (int j = 0; j < 8; j++) {
        unsigned a0 = h2u(__floats2half2_rn(c1[2 * j][0], c1[2 * j][1]));
        unsigned a1 = h2u(__floats2half2_rn(c1[2 * j][2], c1[2 * j][3]));
        unsigned a2 = h2u(__floats2half2_rn(c1[2 * j + 1][0], c1[2 * j + 1][1]));
        unsigned a3 = h2u(__floats2half2_rn(c1[2 * j + 1][2], c1[2 * j + 1][3]));
        int klo = j * 16 + 2 * tc;
#pragma unroll
        for (int nt = 0; nt < 8; nt++) {
            unsigned bb0 = *(const unsigned*)&smh[SW2 + (nt * 8 + tr) * 136 + klo];
            unsigned bb1 = *(const unsigned*)&smh[SW2 + (nt * 8 + tr) * 136 + klo + 8];
            mma16816(c2r[nt], a0, a1, a2, a3, bb0, bb1);
        }
    }

    // epilogue: tsh = fp16(t * dinv)
    int nz0 = base + rbase + tr;
    int nz1 = nz0 + 8;
    float dv0 = (nz0 < n) ? g_dinv[nz0] : 0.f;
    float dv1 = (nz1 < n) ? g_dinv[nz1] : 0.f;
#pragma unroll
    for (int nt = 0; nt < 8; nt++) {
        int col = nt * 8 + 2 * tc;
        if (nz0 < n)
            *(__half2*)&g_tsh[(size_t)nz0 * F + col] =
                __floats2half2_rn(c2r[nt][0] * dv0, c2r[nt][1] * dv0);
        if (nz1 < n)
            *(__half2*)&g_tsh[(size_t)nz1 * F + col] =
                __floats2half2_rn(c2r[nt][2] * dv1, c2r[nt][3] * dv1);
    }
}

// ---------------------------------------------------------------- launch
extern "C" void kernel_launch(void* const* d_in, const int* in_sizes, int n_in,
                              void* d_out, int out_size) {
    const float* x  = (const float*)d_in[0];
    const int* ei   = (const int*)d_in[1];   // int32 edge_index [2, E]
    const float* W1 = (const float*)d_in[2];
    const float* b1 = (const float*)d_in[3];
    const float* W2 = (const float*)d_in[4];
    const float* b2 = (const float*)d_in[5];
    float* out      = (float*)d_out;

    int n = in_sizes[0] / F;   // 100000
    int E = in_sizes[1] / 2;   // 1600000
    const int* src = ei;
    const int* dst = ei + E;

    cudaFuncSetAttribute(k_fused, cudaFuncAttributeMaxDynamicSharedMemorySize,
                         FB_BYTES);

    int nbN = (n + 255) / 256;
    int nbE = (E + 255) / 256;
    int gth_blocks = (n * 32 + 255) / 256;

    cudaLaunchAttribute pdl[1];
    pdl[0].id = cudaLaunchAttributeProgrammaticStreamSerialization;
    pdl[0].val.programmaticStreamSerializationAllowed = 1;

    // CSR build
    k_zero<<<nbN, 256>>>(n);
    k_hist<<<nbE, 256>>>(dst, E);
    k_alloc<<<nbN, 256>>>(n);
    k_permute<<<(E / 2 + 255) / 256, 256>>>(src, dst, E);   // triggers early

    // fp16 prep, PDL: overlaps k_permute (reads only x + dinv from k_alloc)
    {
        cudaLaunchConfig_t cfg = {};
        cfg.gridDim = dim3((n * 16 + 255) / 256);
        cfg.blockDim = dim3(256);
        cfg.stream = 0;
        cfg.attrs = pdl;
        cfg.numAttrs = 1;
        cudaLaunchKernelEx(&cfg, k_prep, x, n);
    }

    // layer 1 aggregation (normal launch; triggers early for k_fused)
    k_gather<0><<<gth_blocks, 256>>>(nullptr, nullptr, n);

    // fused tensor-core double GEMM, PDL: stages weights during gather1 tail
    {
        cudaLaunchConfig_t cfg = {};
        cfg.gridDim = dim3((n + 127) / 128);
        cfg.blockDim = dim3(256);
        cfg.dynamicSmemBytes = FB_BYTES;
        cfg.stream = 0;
        cfg.attrs = pdl;
        cfg.numAttrs = 1;
        cudaLaunchKernelEx(&cfg, k_fused, W1, b1, W2, n);
    }

    // layer 2 aggregation + epilogue, PDL: meta loads during k_fused tail
    {
        cudaLaunchConfig_t cfg = {};
        cfg.gridDim = dim3(gth_blocks);
        cfg.blockDim = dim3(256);
        cfg.stream = 0;
        cfg.attrs = pdl;
        cfg.numAttrs = 1;
        cudaLaunchKernelEx(&cfg, k_gather<1>, b2, out, n);
    }
}